// round 7
// baseline (speedup 1.0000x reference)
#include <cuda_runtime.h>
#include <cuda_bf16.h>
#include <math.h>
#include <float.h>
#include <stdint.h>

// ---------------- problem dims ----------------
#define NB   2048
#define VV   50000
#define E1   1024
#define E2   512
#define CC   2
#define KK   200
#define EMB  300

#define KP   50048              // VV padded to multiple of 32
#define KPW  (KP/2)             // 25024 words per row
#define G1NT (KP / 32)          // 1564 k-tiles

// ---------------- float scratch ----------------------------------------------
#define OFF_EN1    0LL
#define OFF_EN2    (OFF_EN1 + (long long)NB*E1)
#define OFF_PM     (OFF_EN2 + (long long)NB*E2)
#define OFF_LV     (OFF_PM + (long long)NB*CC)
#define OFF_Z      (OFF_LV + (long long)NB*CC)
#define OFF_ZX     (OFF_Z + (long long)NB*CC)
#define OFF_ZC     (OFF_ZX + (long long)NB*CC)
#define OFF_THETA  (OFF_ZC + (long long)KK*CC)
#define OFF_MU1    (OFF_THETA + (long long)NB*KK)
#define OFF_MU2    (OFF_MU1 + (long long)KK*100)
#define OFF_MUZ    (OFF_MU2 + (long long)KK*100)
#define OFF_LOGITS (OFF_MUZ + (long long)KK*EMB)
#define OFF_BETA   (OFF_LOGITS + (long long)KK*VV)
#define OFF_SPM    (OFF_BETA + (long long)KK*VV)
#define OFF_SLV    (OFF_SPM + 4)
#define OFF_SZ     (OFF_SLV + 4)
#define OFF_ST     (OFF_SZ + 4)
#define SCRATCH_FLOATS (OFF_ST + 8)

__device__ float g_scratch[SCRATCH_FLOATS];

// ---------------- bf16 hi/lo planes (words) -----------------------------------
#define WA 51249152LL           // NB * KPW
#define WB 25624576LL           // E1 * KPW
#define W_AH 0LL
#define W_AL (W_AH + WA)
#define W_BH (W_AL + WA)
#define W_BL (W_BH + WB)

__device__ __align__(16) uint32_t g_bf[2*WA + 2*WB];

__device__ __forceinline__ float softplusf(float x) {
    return fmaxf(x, 0.0f) + log1pf(expf(-fabsf(x)));
}

__device__ __forceinline__ uint32_t pk_bf16(float lo, float hi) {
    uint32_t r;
    asm("cvt.rn.bf16x2.f32 %0, %1, %2;" : "=r"(r) : "f"(hi), "f"(lo));
    return r;
}

__device__ __forceinline__ void mma_bf16(float* d,
                                         uint32_t a0, uint32_t a1, uint32_t a2, uint32_t a3,
                                         uint32_t b0, uint32_t b1)
{
    asm volatile(
        "mma.sync.aligned.m16n8k16.row.col.f32.bf16.bf16.f32 "
        "{%0,%1,%2,%3},{%4,%5,%6,%7},{%8,%9},{%0,%1,%2,%3};"
        : "+f"(d[0]), "+f"(d[1]), "+f"(d[2]), "+f"(d[3])
        : "r"(a0), "r"(a1), "r"(a2), "r"(a3), "r"(b0), "r"(b1));
}

__device__ __forceinline__ void ldsm_x4(uint32_t& r0, uint32_t& r1, uint32_t& r2,
                                        uint32_t& r3, uint32_t addr)
{
    asm volatile("ldmatrix.sync.aligned.m8n8.x4.shared.b16 {%0,%1,%2,%3}, [%4];"
                 : "=r"(r0), "=r"(r1), "=r"(r2), "=r"(r3) : "r"(addr));
}

// =============================================================================
// Pre-pass: split input (2048 rows) and en1_W (1024 rows) into bf16 hi/lo
// planes, rows padded to KP with zeros.
// =============================================================================
__global__ void __launch_bounds__(256)
split_bf16(const float* __restrict__ A, const float* __restrict__ B)
{
    const int b = blockIdx.x, tid = threadIdx.x;
    const float* src;
    uint32_t *h, *l;
    if (b < NB) {
        src = A + (size_t)b * VV;
        h = g_bf + W_AH + (size_t)b * KPW;
        l = g_bf + W_AL + (size_t)b * KPW;
    } else {
        int r = b - NB;
        src = B + (size_t)r * VV;
        h = g_bf + W_BH + (size_t)r * KPW;
        l = g_bf + W_BL + (size_t)r * KPW;
    }
    for (int i = tid; i < VV / 4; i += 256) {
        float4 v = *reinterpret_cast<const float4*>(src + i * 4);
        __nv_bfloat16 hx = __float2bfloat16_rn(v.x), hy = __float2bfloat16_rn(v.y);
        __nv_bfloat16 hz = __float2bfloat16_rn(v.z), hw = __float2bfloat16_rn(v.w);
        h[2*i]     = ((uint32_t)__bfloat16_as_ushort(hy) << 16) | __bfloat16_as_ushort(hx);
        h[2*i + 1] = ((uint32_t)__bfloat16_as_ushort(hw) << 16) | __bfloat16_as_ushort(hz);
        l[2*i]     = pk_bf16(v.x - __bfloat162float(hx), v.y - __bfloat162float(hy));
        l[2*i + 1] = pk_bf16(v.z - __bfloat162float(hz), v.w - __bfloat162float(hw));
    }
    if (tid < KPW - VV/2) {
        h[VV/2 + tid] = 0u;
        l[VV/2 + tid] = 0u;
    }
}

// =============================================================================
// GEMM1: en1 = softplus(input @ en1_W^T + b), 3xbf16 from pre-split planes.
// Block tile 128x64, BK=32, 256 threads (8 warps, 32x32 warp tiles),
// grid (16,16)=256 CTAs, 2 CTAs/SM. 3-stage cp.async. ldmatrix fragments.
// Stage layout (bytes): Ah[128x80] @0, Al @10240, Bh[64x80] @20480, Bl @25600.
// =============================================================================
#define STG    30720
#define G1_SMEM (3 * STG)          // 92160 B

__global__ void __launch_bounds__(256, 2)
gemm1_pre(const float* __restrict__ bias, float* __restrict__ C)
{
    extern __shared__ __align__(16) char sm[];
    const uint32_t sb32 = (uint32_t)__cvta_generic_to_shared(sm);
    const int tid = threadIdx.x;
    const int lane = tid & 31, warp = tid >> 5;
    const int gid = lane >> 2, tig = lane & 3;
    const int wm = warp >> 1, wn = warp & 1;           // 4 x 2 warps
    const int m0 = blockIdx.y * 128, n0 = blockIdx.x * 64;

    float acc[2][4][4];
#pragma unroll
    for (int i = 0; i < 2; i++)
#pragma unroll
        for (int j = 0; j < 4; j++)
#pragma unroll
            for (int l = 0; l < 4; l++) acc[i][j][l] = 0.0f;

    // ---- cp.async source/dst assignments (6 chunks of 16B per thread) ----
    const uint32_t* gsrc[6];
    uint32_t sdst[6];
#pragma unroll
    for (int i = 0; i < 4; i++) {          // A: 2 planes x 128 rows x 4 parts
        int idx = tid + i * 256;
        int p = idx >> 9, r = (idx >> 2) & 127, part = idx & 3;
        gsrc[i] = g_bf + (p ? W_AL : W_AH) + (size_t)(m0 + r) * KPW + part * 4;
        sdst[i] = sb32 + (uint32_t)(p * 10240 + r * 80 + part * 16);
    }
#pragma unroll
    for (int i = 0; i < 2; i++) {          // B: 2 planes x 64 rows x 4 parts
        int idx = tid + i * 256;
        int p = idx >> 8, r = (idx >> 2) & 63, part = idx & 3;
        gsrc[4 + i] = g_bf + (p ? W_BL : W_BH) + (size_t)(n0 + r) * KPW + part * 4;
        sdst[4 + i] = sb32 + (uint32_t)(20480 + p * 5120 + r * 80 + part * 16);
    }

    auto issue = [&](int t) {
        const uint32_t boff = (uint32_t)(t % 3) * STG;
        const size_t k = (size_t)t * 16;   // words per k-tile
#pragma unroll
        for (int i = 0; i < 6; i++)
            asm volatile("cp.async.cg.shared.global [%0], [%1], 16;"
                         :: "r"(sdst[i] + boff), "l"(gsrc[i] + k) : "memory");
        asm volatile("cp.async.commit_group;" ::: "memory");
    };

    // ---- ldmatrix lane offsets ----
    const int lr = (lane & 7) + ((lane >> 3) & 1) * 8;   // row within 16
    const int kb = ((lane >> 4) & 1) * 16;               // byte within 32B k-block
    const uint32_t aoff = (uint32_t)((wm * 32 + lr) * 80 + kb);          // Ah base
    const uint32_t boff2 = (uint32_t)(20480 + (wn * 32 + lr) * 80 + kb); // Bh base

    issue(0);
    issue(1);

    for (int t = 0; t < G1NT; t++) {
        if (t == G1NT - 1) asm volatile("cp.async.wait_group 0;" ::: "memory");
        else               asm volatile("cp.async.wait_group 1;" ::: "memory");
        __syncthreads();
        if (t + 2 < G1NT) issue(t + 2);

        const uint32_t st = sb32 + (uint32_t)(t % 3) * STG;
#pragma unroll
        for (int kkw = 0; kkw < 2; kkw++) {
            const uint32_t ka = st + kkw * 32;
            uint32_t ah[2][4], al[2][4], bq[2][4], blq[2][4];
#pragma unroll
            for (int ms = 0; ms < 2; ms++) {
                ldsm_x4(ah[ms][0], ah[ms][1], ah[ms][2], ah[ms][3],
                        ka + aoff + ms * 1280);
                ldsm_x4(al[ms][0], al[ms][1], al[ms][2], al[ms][3],
                        ka + aoff + ms * 1280 + 10240);
            }
#pragma unroll
            for (int pr = 0; pr < 2; pr++) {
                ldsm_x4(bq[pr][0], bq[pr][1], bq[pr][2], bq[pr][3],
                        ka + boff2 + pr * 1280);
                ldsm_x4(blq[pr][0], blq[pr][1], blq[pr][2], blq[pr][3],
                        ka + boff2 + pr * 1280 + 5120);
            }
            // bh[ns] pairs: ns=2*pr+j -> {bq[pr][j], bq[pr][j+2]}
#pragma unroll
            for (int ms = 0; ms < 2; ms++)
#pragma unroll
                for (int pr = 0; pr < 2; pr++)
#pragma unroll
                    for (int j = 0; j < 2; j++) {
                        int ns = pr * 2 + j;
                        mma_bf16(acc[ms][ns], ah[ms][0], ah[ms][1], ah[ms][2], ah[ms][3],
                                 bq[pr][j], bq[pr][j + 2]);
                        mma_bf16(acc[ms][ns], ah[ms][0], ah[ms][1], ah[ms][2], ah[ms][3],
                                 blq[pr][j], blq[pr][j + 2]);
                        mma_bf16(acc[ms][ns], al[ms][0], al[ms][1], al[ms][2], al[ms][3],
                                 bq[pr][j], bq[pr][j + 2]);
                    }
        }
    }

    // epilogue: bias + softplus; warp tile rows m0+wm*32, cols n0+wn*32
#pragma unroll
    for (int ms = 0; ms < 2; ms++) {
        const int r0 = m0 + wm * 32 + ms * 16 + gid;
#pragma unroll
        for (int ns = 0; ns < 4; ns++) {
            const int c0 = n0 + wn * 32 + ns * 8 + 2 * tig;
            const float bv0 = bias[c0], bv1 = bias[c0 + 1];
            C[(size_t)r0 * E1 + c0]           = softplusf(acc[ms][ns][0] + bv0);
            C[(size_t)r0 * E1 + c0 + 1]       = softplusf(acc[ms][ns][1] + bv1);
            C[(size_t)(r0 + 8) * E1 + c0]     = softplusf(acc[ms][ns][2] + bv0);
            C[(size_t)(r0 + 8) * E1 + c0 + 1] = softplusf(acc[ms][ns][3] + bv1);
        }
    }
}

// ============================ bf16x3 NT GEMM (en2 + logits) ==================
#define NTB_SMEM (2 * 10240 * 4)

template<bool SP, bool HB, bool CHKMN>
__global__ void __launch_bounds__(512, 1)
gemm_nt_bf16x3(const float* __restrict__ A, const float* __restrict__ B,
               const float* __restrict__ bias, float* __restrict__ C,
               int M, int N, int K)
{
    extern __shared__ __align__(16) uint32_t sw[];
    const int tid = threadIdx.x;
    const int lane = tid & 31, warp = tid >> 5;
    const int gid = lane >> 2, tig = lane & 3;
    const int wm = warp >> 2, wn = warp & 3;
    const int m0 = blockIdx.y * 128, n0 = blockIdx.x * 128;
    const int nt = (K + 31) / 32;

    float acc[2][4][4];
#pragma unroll
    for (int i = 0; i < 2; i++)
#pragma unroll
        for (int j = 0; j < 4; j++)
#pragma unroll
            for (int l = 0; l < 4; l++) acc[i][j][l] = 0.0f;

    const int srow = tid >> 3;
    const int sq   = tid & 7;
    float4 stA[2], stB[2];

    auto load_tile = [&](int t) {
        const int gk = t * 32 + sq * 4;
#pragma unroll
        for (int l = 0; l < 2; l++) {
            int r = srow + l * 64;
            {
                int gm = m0 + r;
                float4 v = make_float4(0.f, 0.f, 0.f, 0.f);
                if (((!CHKMN) || gm < M)) {
                    if (gk + 3 < K) v = *reinterpret_cast<const float4*>(A + (size_t)gm * K + gk);
                    else if (gk < K) {
                        const float* p = A + (size_t)gm * K;
                        v.x = p[gk];
                        if (gk + 1 < K) v.y = p[gk + 1];
                        if (gk + 2 < K) v.z = p[gk + 2];
                    }
                }
                stA[l] = v;
            }
            {
                int gn = n0 + r;
                float4 v = make_float4(0.f, 0.f, 0.f, 0.f);
                if (((!CHKMN) || gn < N)) {
                    if (gk + 3 < K) v = *reinterpret_cast<const float4*>(B + (size_t)gn * K + gk);
                    else if (gk < K) {
                        const float* p = B + (size_t)gn * K;
                        v.x = p[gk];
                        if (gk + 1 < K) v.y = p[gk + 1];
                        if (gk + 2 < K) v.z = p[gk + 2];
                    }
                }
                stB[l] = v;
            }
        }
    };

    auto store_tile = [&](uint32_t* buf) {
#pragma unroll
        for (int l = 0; l < 2; l++) {
            int r = srow + l * 64;
            uint32_t w = (uint32_t)(r * 20 + sq * 2);
            {
                float4 v = stA[l];
                __nv_bfloat16 hx = __float2bfloat16_rn(v.x), hy = __float2bfloat16_rn(v.y);
                __nv_bfloat16 hz = __float2bfloat16_rn(v.z), hw = __float2bfloat16_rn(v.w);
                buf[w]     = ((uint32_t)__bfloat16_as_ushort(hy) << 16) | __bfloat16_as_ushort(hx);
                buf[w + 1] = ((uint32_t)__bfloat16_as_ushort(hw) << 16) | __bfloat16_as_ushort(hz);
                buf[w + 2560]     = pk_bf16(v.x - __bfloat162float(hx), v.y - __bfloat162float(hy));
                buf[w + 2560 + 1] = pk_bf16(v.z - __bfloat162float(hz), v.w - __bfloat162float(hw));
            }
            {
                float4 v = stB[l];
                __nv_bfloat16 hx = __float2bfloat16_rn(v.x), hy = __float2bfloat16_rn(v.y);
                __nv_bfloat16 hz = __float2bfloat16_rn(v.z), hw = __float2bfloat16_rn(v.w);
                buf[w + 5120]     = ((uint32_t)__bfloat16_as_ushort(hy) << 16) | __bfloat16_as_ushort(hx);
                buf[w + 5120 + 1] = ((uint32_t)__bfloat16_as_ushort(hw) << 16) | __bfloat16_as_ushort(hz);
                buf[w + 7680]     = pk_bf16(v.x - __bfloat162float(hx), v.y - __bfloat162float(hy));
                buf[w + 7680 + 1] = pk_bf16(v.z - __bfloat162float(hz), v.w - __bfloat162float(hw));
            }
        }
    };

    load_tile(0);
    store_tile(sw);
    __syncthreads();

    for (int t = 0; t < nt; t++) {
        const int b = t & 1;
        uint32_t* bb = sw + b * 10240;
        if (t + 1 < nt) load_tile(t + 1);

#pragma unroll
        for (int kkw = 0; kkw < 16; kkw += 8) {
            uint32_t ah[2][4], al[2][4], bh[4][2], bl[4][2];
#pragma unroll
            for (int ms = 0; ms < 2; ms++) {
                int base = (wm * 32 + ms * 16 + gid) * 20 + kkw + tig;
                ah[ms][0] = bb[base];       ah[ms][1] = bb[base + 160];
                ah[ms][2] = bb[base + 4];   ah[ms][3] = bb[base + 164];
                al[ms][0] = bb[base + 2560];       al[ms][1] = bb[base + 2560 + 160];
                al[ms][2] = bb[base + 2560 + 4];   al[ms][3] = bb[base + 2560 + 164];
            }
#pragma unroll
            for (int ns = 0; ns < 4; ns++) {
                int base = 5120 + (wn * 32 + ns * 8 + gid) * 20 + kkw + tig;
                bh[ns][0] = bb[base];       bh[ns][1] = bb[base + 4];
                bl[ns][0] = bb[base + 2560]; bl[ns][1] = bb[base + 2560 + 4];
            }
#pragma unroll
            for (int ms = 0; ms < 2; ms++)
#pragma unroll
                for (int ns = 0; ns < 4; ns++) {
                    mma_bf16(acc[ms][ns], ah[ms][0], ah[ms][1], ah[ms][2], ah[ms][3],
                             bh[ns][0], bh[ns][1]);
                    mma_bf16(acc[ms][ns], ah[ms][0], ah[ms][1], ah[ms][2], ah[ms][3],
                             bl[ns][0], bl[ns][1]);
                    mma_bf16(acc[ms][ns], al[ms][0], al[ms][1], al[ms][2], al[ms][3],
                             bh[ns][0], bh[ns][1]);
                }
        }

        if (t + 1 < nt) store_tile(sw + (b ^ 1) * 10240);
        __syncthreads();
    }

#pragma unroll
    for (int ms = 0; ms < 2; ms++) {
        int r0 = m0 + wm * 32 + ms * 16 + gid;
#pragma unroll
        for (int ns = 0; ns < 4; ns++) {
            int c0 = n0 + wn * 32 + ns * 8 + 2 * tig;
            float bv0 = 0.f, bv1 = 0.f;
            if (HB) { bv0 = bias[c0]; bv1 = bias[c0 + 1]; }
            float v00 = acc[ms][ns][0] + bv0;
            float v01 = acc[ms][ns][1] + bv1;
            float v10 = acc[ms][ns][2] + bv0;
            float v11 = acc[ms][ns][3] + bv1;
            if (SP) { v00 = softplusf(v00); v01 = softplusf(v01);
                      v10 = softplusf(v10); v11 = softplusf(v11); }
            if (!CHKMN) {
                C[(size_t)r0 * N + c0]           = v00;
                C[(size_t)r0 * N + c0 + 1]       = v01;
                C[(size_t)(r0 + 8) * N + c0]     = v10;
                C[(size_t)(r0 + 8) * N + c0 + 1] = v11;
            } else {
                if (r0 < M) {
                    if (c0 < N)     C[(size_t)r0 * N + c0]     = v00;
                    if (c0 + 1 < N) C[(size_t)r0 * N + c0 + 1] = v01;
                }
                if (r0 + 8 < M) {
                    if (c0 < N)     C[(size_t)(r0 + 8) * N + c0]     = v10;
                    if (c0 + 1 < N) C[(size_t)(r0 + 8) * N + c0 + 1] = v11;
                }
            }
        }
    }
}

// ============================ tf32 recon =====================================
__device__ __forceinline__ unsigned tf32_rna(float x) {
    unsigned r;
    asm("cvt.rna.tf32.f32 %0, %1;" : "=r"(r) : "f"(x));
    return r;
}

__device__ __forceinline__ void mma_tf32(float* d,
                                         unsigned a0, unsigned a1, unsigned a2, unsigned a3,
                                         unsigned b0, unsigned b1)
{
    asm volatile(
        "mma.sync.aligned.m16n8k8.row.col.f32.tf32.tf32.f32 "
        "{%0,%1,%2,%3},{%4,%5,%6,%7},{%8,%9},{%0,%1,%2,%3};"
        : "+f"(d[0]), "+f"(d[1]), "+f"(d[2]), "+f"(d[3])
        : "r"(a0), "r"(a1), "r"(a2), "r"(a3), "r"(b0), "r"(b1));
}

__global__ void __launch_bounds__(256, 2)
recon_tf32(const float* __restrict__ A, const float* __restrict__ B,
           float* __restrict__ C)
{
    __shared__ float Ah[128][20];
    __shared__ float Bh[16][136];
    const int tid = threadIdx.x;
    const int lane = tid & 31, warp = tid >> 5;
    const int gid = lane >> 2, tig = lane & 3;
    const int wm = warp >> 1, wn = warp & 1;
    const int m0 = blockIdx.y * 128;
    const int n0 = blockIdx.x * 128;

    float acc[2][8][4];
#pragma unroll
    for (int i = 0; i < 2; i++)
#pragma unroll
        for (int j = 0; j < 8; j++)
#pragma unroll
            for (int l = 0; l < 4; l++) acc[i][j][l] = 0.0f;

    for (int k0 = 0; k0 < KK; k0 += 16) {
#pragma unroll
        for (int l = 0; l < 2; l++) {
            int idx = tid + l * 256;
            int row = idx >> 2, kq = (idx & 3) * 4;
            int gk = k0 + kq;
            float4 v = make_float4(0.f, 0.f, 0.f, 0.f);
            if (gk + 3 < KK)
                v = *reinterpret_cast<const float4*>(A + (size_t)(m0 + row) * KK + gk);
            Ah[row][kq + 0] = __uint_as_float(tf32_rna(v.x));
            Ah[row][kq + 1] = __uint_as_float(tf32_rna(v.y));
            Ah[row][kq + 2] = __uint_as_float(tf32_rna(v.z));
            Ah[row][kq + 3] = __uint_as_float(tf32_rna(v.w));
        }
#pragma unroll
        for (int l = 0; l < 2; l++) {
            int idx = tid + l * 256;
            int kk = idx >> 5, nc = (idx & 31) * 4;
            int gk = k0 + kk, gn = n0 + nc;
            float4 v = make_float4(0.f, 0.f, 0.f, 0.f);
            if (gk < KK && gn + 3 < VV)
                v = *reinterpret_cast<const float4*>(B + (size_t)gk * VV + gn);
            Bh[kk][nc + 0] = __uint_as_float(tf32_rna(v.x));
            Bh[kk][nc + 1] = __uint_as_float(tf32_rna(v.y));
            Bh[kk][nc + 2] = __uint_as_float(tf32_rna(v.z));
            Bh[kk][nc + 3] = __uint_as_float(tf32_rna(v.w));
        }
        __syncthreads();

#pragma unroll
        for (int kk = 0; kk < 16; kk += 8) {
            unsigned a[2][4], b[8][2];
#pragma unroll
            for (int ms = 0; ms < 2; ms++) {
                int r = wm * 32 + ms * 16 + gid;
                a[ms][0] = __float_as_uint(Ah[r][kk + tig]);
                a[ms][1] = __float_as_uint(Ah[r + 8][kk + tig]);
                a[ms][2] = __float_as_uint(Ah[r][kk + tig + 4]);
                a[ms][3] = __float_as_uint(Ah[r + 8][kk + tig + 4]);
            }
#pragma unroll
            for (int ns = 0; ns < 8; ns++) {
                int n = wn * 64 + ns * 8 + gid;
                b[ns][0] = __float_as_uint(Bh[kk + tig][n]);
                b[ns][1] = __float_as_uint(Bh[kk + tig + 4][n]);
            }
#pragma unroll
            for (int ms = 0; ms < 2; ms++)
#pragma unroll
                for (int ns = 0; ns < 8; ns++)
                    mma_tf32(acc[ms][ns], a[ms][0], a[ms][1], a[ms][2], a[ms][3],
                             b[ns][0], b[ns][1]);
        }
        __syncthreads();
    }

#pragma unroll
    for (int ms = 0; ms < 2; ms++) {
        int r0 = m0 + wm * 32 + ms * 16 + gid;
#pragma unroll
        for (int ns = 0; ns < 8; ns++) {
            int c0 = n0 + wn * 64 + ns * 8 + 2 * tig;
            if (c0 < VV) {
                C[(size_t)r0 * VV + c0]       = acc[ms][ns][0];
                C[(size_t)(r0 + 8) * VV + c0] = acc[ms][ns][2];
            }
            if (c0 + 1 < VV) {
                C[(size_t)r0 * VV + c0 + 1]       = acc[ms][ns][1];
                C[(size_t)(r0 + 8) * VV + c0 + 1] = acc[ms][ns][3];
            }
        }
    }
}

// ---------------- mean / logvar heads ---------------------------------------
__global__ void meanlogvar_kernel(const float* __restrict__ en2,
                                  const float* __restrict__ mW, const float* __restrict__ mb,
                                  const float* __restrict__ lW, const float* __restrict__ lb,
                                  float* __restrict__ pm, float* __restrict__ lv)
{
    int t = blockIdx.x * blockDim.x + threadIdx.x;
    if (t >= NB * 4) return;
    int n = t >> 2, j = t & 3;
    const float* w = (j < 2) ? (mW + j * E2) : (lW + (j - 2) * E2);
    const float* x = en2 + (size_t)n * E2;
    float s = 0.f;
    for (int i = 0; i < E2; i += 4) {
        float4 xa = *reinterpret_cast<const float4*>(x + i);
        float4 wa = *reinterpret_cast<const float4*>(w + i);
        s += xa.x * wa.x + xa.y * wa.y + xa.z * wa.z + xa.w * wa.w;
    }
    if (j < 2) pm[n * 2 + j] = s + mb[j];
    else       lv[n * 2 + (j - 2)] = s + lb[j - 2];
}

// ---------------- column stats of (R x 2) -----------------------------------
__global__ void colstats_kernel(const float* __restrict__ X, int R, float* __restrict__ out)
{
    __shared__ float ss[256], s2[256];
    int c = blockIdx.x, tid = threadIdx.x;
    float s = 0.f, q = 0.f;
    for (int r = tid; r < R; r += 256) {
        float x = X[r * 2 + c];
        s += x; q += x * x;
    }
    ss[tid] = s; s2[tid] = q;
    __syncthreads();
    for (int st = 128; st > 0; st >>= 1) {
        if (tid < st) { ss[tid] += ss[tid + st]; s2[tid] += s2[tid + st]; }
        __syncthreads();
    }
    if (tid == 0) {
        float m = ss[0] / R;
        out[c] = m;
        out[2 + c] = s2[0] / R - m * m;
    }
}

// ---------------- z ----------------------------------------------------------
__global__ void z_kernel(const float* __restrict__ pm, const float* __restrict__ lv,
                         const float* __restrict__ spm, const float* __restrict__ slv,
                         const float* __restrict__ gm, const float* __restrict__ bm,
                         const float* __restrict__ gl, const float* __restrict__ bl,
                         const float* __restrict__ eps,
                         float* __restrict__ gz, float* __restrict__ outz)
{
    int idx = blockIdx.x * 256 + threadIdx.x;
    if (idx >= NB * CC) return;
    int c = idx & 1;
    float pmb = gm[c] * (pm[idx] - spm[c]) * rsqrtf(spm[2 + c] + 1e-5f) + bm[c];
    float lvb = gl[c] * (lv[idx] - slv[c]) * rsqrtf(slv[2 + c] + 1e-5f) + bl[c];
    float z = pmb + sqrtf(expf(lvb)) * eps[idx];
    gz[idx] = z;
    outz[idx] = z;
}

// ---------------- BN apply ---------------------------------------------------
__global__ void bn_apply_kernel(const float* __restrict__ X, const float* __restrict__ stats,
                                const float* __restrict__ g, const float* __restrict__ b,
                                int total, float* __restrict__ o1, float* __restrict__ o2)
{
    int idx = blockIdx.x * 256 + threadIdx.x;
    if (idx >= total) return;
    int c = idx & 1;
    float y = g[c] * (X[idx] - stats[c]) * rsqrtf(stats[2 + c] + 1e-5f) + b[c];
    o1[idx] = y;
    o2[idx] = y;
}

// ---------------- theta ------------------------------------------------------
__global__ void theta_kernel(const float* __restrict__ zx, const float* __restrict__ zc,
                             float* __restrict__ gtheta, float* __restrict__ otheta)
{
    __shared__ float sz[KK * 2];
    __shared__ float red[256];
    int n = blockIdx.x, tid = threadIdx.x;
    for (int i = tid; i < KK * 2; i += 256) sz[i] = zc[i];
    __syncthreads();
    float x0 = zx[n * 2], x1 = zx[n * 2 + 1];
    float l = -FLT_MAX;
    if (tid < KK) {
        float dx = x0 - sz[tid * 2];
        float dy = x1 - sz[tid * 2 + 1];
        l = -0.5f * (dx * dx + dy * dy);
    }
    red[tid] = l;
    __syncthreads();
    for (int st = 128; st > 0; st >>= 1) {
        if (tid < st) red[tid] = fmaxf(red[tid], red[tid + st]);
        __syncthreads();
    }
    float mx = red[0];
    __syncthreads();
    float e = (tid < KK) ? expf(l - mx) : 0.f;
    red[tid] = e;
    __syncthreads();
    for (int st = 128; st > 0; st >>= 1) {
        if (tid < st) red[tid] += red[tid + st];
        __syncthreads();
    }
    float inv = 1.f / red[0];
    if (tid < KK) {
        float th = e * inv;
        gtheta[(size_t)n * KK + tid] = th;
        otheta[(size_t)n * KK + tid] = th;
    }
}

// ---------------- decoder MLP ------------------------------------------------
__global__ void mu1_kernel(const float* __restrict__ zc, const float* __restrict__ W,
                           const float* __restrict__ b, float* __restrict__ out)
{
    int t = blockIdx.x * 256 + threadIdx.x;
    if (t >= KK * 100) return;
    int k = t / 100, j = t % 100;
    float v = zc[k * 2] * W[j * 2] + zc[k * 2 + 1] * W[j * 2 + 1] + b[j];
    out[t] = softplusf(v);
}

__global__ void mu2_kernel(const float* __restrict__ mu1, const float* __restrict__ W,
                           const float* __restrict__ b, float* __restrict__ out)
{
    __shared__ float row[100];
    int k = blockIdx.x, tid = threadIdx.x;
    if (tid < 100) row[tid] = mu1[k * 100 + tid];
    __syncthreads();
    if (tid < 100) {
        const float* w = W + tid * 100;
        float s = b[tid];
        for (int i = 0; i < 100; i++) s += row[i] * w[i];
        out[k * 100 + tid] = softplusf(s);
    }
}

__global__ void muz_kernel(const float* __restrict__ mu2, const float* __restrict__ W,
                           const float* __restrict__ b, float* __restrict__ out)
{
    __shared__ float row[100];
    int k = blockIdx.x, tid = threadIdx.x;
    if (tid < 100) row[tid] = mu2[k * 100 + tid];
    __syncthreads();
    for (int j = tid; j < EMB; j += 128) {
        const float* w = W + j * 100;
        float s = b[j];
        for (int i = 0; i < 100; i++) s += row[i] * w[i];
        out[k * EMB + j] = s;
    }
}

// ---------------- beta -------------------------------------------------------
__global__ void __launch_bounds__(1024)
beta_kernel(const float* __restrict__ logits, const float* __restrict__ bbias,
            const float* __restrict__ gdec, const float* __restrict__ bdec,
            float* __restrict__ beta)
{
    __shared__ float red[1024];
    __shared__ float red2[1024];
    const int k = blockIdx.x, tid = threadIdx.x;
    const float* row = logits + (size_t)k * VV;
    const float* bb  = bbias + (size_t)k * VV;

    float s = 0.f, q = 0.f;
    for (int v = tid; v < VV; v += 1024) { float x = row[v]; s += x; q += x * x; }
    red[tid] = s; red2[tid] = q;
    __syncthreads();
    for (int st = 512; st > 0; st >>= 1) {
        if (tid < st) { red[tid] += red[tid + st]; red2[tid] += red2[tid + st]; }
        __syncthreads();
    }
    float mean = red[0] / VV;
    float var  = red2[0] / VV - mean * mean;
    float scale = gdec[k] * rsqrtf(var + 1e-5f);
    float shift = bdec[k] - mean * scale;
    __syncthreads();

    float mx = -FLT_MAX;
    for (int v = tid; v < VV; v += 1024) {
        float y = row[v] * scale + shift + bb[v];
        mx = fmaxf(mx, y);
    }
    red[tid] = mx;
    __syncthreads();
    for (int st = 512; st > 0; st >>= 1) {
        if (tid < st) red[tid] = fmaxf(red[tid], red[tid + st]);
        __syncthreads();
    }
    mx = red[0];
    __syncthreads();

    float se = 0.f;
    for (int v = tid; v < VV; v += 1024) {
        float y = row[v] * scale + shift + bb[v];
        se += expf(y - mx);
    }
    red[tid] = se;
    __syncthreads();
    for (int st = 512; st > 0; st >>= 1) {
        if (tid < st) red[tid] += red[tid + st];
        __syncthreads();
    }
    float inv = 1.f / red[0];

    for (int v = tid; v < VV; v += 1024) {
        float y = row[v] * scale + shift + bb[v];
        beta[(size_t)k * VV + v] = expf(y - mx) * inv;
    }
}

// ---------------- launch -----------------------------------------------------
extern "C" void kernel_launch(void* const* d_in, const int* in_sizes, int n_in,
                              void* d_out, int out_size)
{
    const float* input_   = (const float*)d_in[0];
    const float* eps      = (const float*)d_in[2];
    const float* en1_W    = (const float*)d_in[3];
    const float* en1_b    = (const float*)d_in[4];
    const float* en2_W    = (const float*)d_in[5];
    const float* en2_b    = (const float*)d_in[6];
    const float* mean_W   = (const float*)d_in[7];
    const float* mean_b   = (const float*)d_in[8];
    const float* logvar_W = (const float*)d_in[9];
    const float* logvar_b = (const float*)d_in[10];
    const float* mu1_W    = (const float*)d_in[11];
    const float* mu1_b    = (const float*)d_in[12];
    const float* mu2_W    = (const float*)d_in[13];
    const float* mu2_b    = (const float*)d_in[14];
    const float* mu_W     = (const float*)d_in[15];
    const float* mu_b     = (const float*)d_in[16];
    const float* topics   = (const float*)d_in[17];
    const float* bbias    = (const float*)d_in[18];
    const float* emb      = (const float*)d_in[19];
    const float* g_mean   = (const float*)d_in[20];
    const float* b_mean   = (const float*)d_in[21];
    const float* g_logvar = (const float*)d_in[22];
    const float* b_logvar = (const float*)d_in[23];
    const float* g_x      = (const float*)d_in[24];
    const float* b_x      = (const float*)d_in[25];
    const float* g_phi    = (const float*)d_in[26];
    const float* b_phi    = (const float*)d_in[27];
    const float* g_dec    = (const float*)d_in[28];
    const float* b_dec    = (const float*)d_in[29];

    float* out = (float*)d_out;
    float* out_z     = out;
    float* out_recon = out + (long long)NB * CC;
    float* out_zx    = out_recon + (long long)NB * VV;
    float* out_zc    = out_zx + (long long)NB * CC;
    float* out_theta = out_zc + (long long)KK * CC;

    void* sp = nullptr;
    cudaGetSymbolAddress(&sp, g_scratch);
    float* S = (float*)sp;
    float* s_en1    = S + OFF_EN1;
    float* s_en2    = S + OFF_EN2;
    float* s_pm     = S + OFF_PM;
    float* s_lv     = S + OFF_LV;
    float* s_z      = S + OFF_Z;
    float* s_zx     = S + OFF_ZX;
    float* s_zc     = S + OFF_ZC;
    float* s_theta  = S + OFF_THETA;
    float* s_mu1    = S + OFF_MU1;
    float* s_mu2    = S + OFF_MU2;
    float* s_muz    = S + OFF_MUZ;
    float* s_logits = S + OFF_LOGITS;
    float* s_beta   = S + OFF_BETA;
    float* st_pm    = S + OFF_SPM;
    float* st_lv    = S + OFF_SLV;
    float* st_z     = S + OFF_SZ;
    float* st_t     = S + OFF_ST;

    cudaFuncSetAttribute(gemm1_pre, cudaFuncAttributeMaxDynamicSharedMemorySize, G1_SMEM);
    cudaFuncSetAttribute(gemm_nt_bf16x3<true, true, false>,
                         cudaFuncAttributeMaxDynamicSharedMemorySize, NTB_SMEM);
    cudaFuncSetAttribute(gemm_nt_bf16x3<false, false, true>,
                         cudaFuncAttributeMaxDynamicSharedMemorySize, NTB_SMEM);

    // 0) pre-split input + en1_W into bf16 hi/lo planes
    split_bf16<<<NB + E1, 256>>>(input_, en1_W);

    // 1-4) decoder-side small kernels (independent of encoder)
    colstats_kernel<<<2, 256>>>(topics, KK, st_t);
    bn_apply_kernel<<<(KK * CC + 255) / 256, 256>>>(topics, st_t, g_phi, b_phi, KK * CC, s_zc, out_zc);
    mu1_kernel<<<(KK * 100 + 255) / 256, 256>>>(s_zc, mu1_W, mu1_b, s_mu1);
    mu2_kernel<<<KK, 128>>>(s_mu1, mu2_W, mu2_b, s_mu2);

    // 5) en1 = softplus(input @ en1_W^T + b) — bf16x3, ldmatrix, 2 CTA/SM
    gemm1_pre<<<dim3(E1 / 64, NB / 128), 256, G1_SMEM>>>(en1_b, s_en1);

    // 6) muz
    muz_kernel<<<KK, 128>>>(s_mu2, mu_W, mu_b, s_muz);

    // 7) en2 — bf16x3
    gemm_nt_bf16x3<true, true, false><<<dim3(E2 / 128, NB / 128), 512, NTB_SMEM>>>(
        s_en1, en2_W, en2_b, s_en2, NB, E2, E1);

    // 8) heads
    meanlogvar_kernel<<<(NB * 4 + 255) / 256, 256>>>(
        s_en2, mean_W, mean_b, logvar_W, logvar_b, s_pm, s_lv);

    // 9-11) BN stats + z
    colstats_kernel<<<2, 256>>>(s_pm, NB, st_pm);
    colstats_kernel<<<2, 256>>>(s_lv, NB, st_lv);
    z_kernel<<<(NB * CC + 255) / 256, 256>>>(
        s_pm, s_lv, st_pm, st_lv, g_mean, b_mean, g_logvar, b_logvar, eps, s_z, out_z);

    // 12-13) zx
    colstats_kernel<<<2, 256>>>(s_z, NB, st_z);
    bn_apply_kernel<<<(NB * CC + 255) / 256, 256>>>(s_z, st_z, g_x, b_x, NB * CC, s_zx, out_zx);

    // 14) theta
    theta_kernel<<<NB, 256>>>(s_zx, s_zc, s_theta, out_theta);

    // 15) logits = mu_z @ emb^T — bf16x3
    gemm_nt_bf16x3<false, false, true><<<dim3((VV + 127) / 128, (KK + 127) / 128), 512, NTB_SMEM>>>(
        s_muz, emb, nullptr, s_logits, KK, VV, EMB);

    // 16) beta
    beta_kernel<<<KK, 1024>>>(s_logits, bbias, g_dec, b_dec, s_beta);

    // 17) recon = theta @ beta
    recon_tf32<<<dim3((VV + 127) / 128, NB / 128), 256>>>(s_theta, s_beta, out_recon);

    (void)in_sizes; (void)n_in; (void)out_size;
}

// round 8
// speedup vs baseline: 1.3125x; 1.3125x over previous
#include <cuda_runtime.h>
#include <cuda_bf16.h>
#include <cuda_fp16.h>
#include <math.h>
#include <float.h>
#include <stdint.h>

// ---------------- problem dims ----------------
#define NB   2048
#define VV   50000
#define E1   1024
#define E2   512
#define CC   2
#define KK   200
#define EMB  300

#define KP   50048              // VV padded to multiple of 32
#define KPW  (KP/2)             // 25024 words per row
#define G1NT (KP / 32)          // 1564 k-tiles

// ---------------- float scratch ----------------------------------------------
#define OFF_EN1    0LL
#define OFF_EN2    (OFF_EN1 + (long long)NB*E1)
#define OFF_PM     (OFF_EN2 + (long long)NB*E2)
#define OFF_LV     (OFF_PM + (long long)NB*CC)
#define OFF_Z      (OFF_LV + (long long)NB*CC)
#define OFF_ZX     (OFF_Z + (long long)NB*CC)
#define OFF_ZC     (OFF_ZX + (long long)NB*CC)
#define OFF_THETA  (OFF_ZC + (long long)KK*CC)
#define OFF_MU1    (OFF_THETA + (long long)NB*KK)
#define OFF_MU2    (OFF_MU1 + (long long)KK*100)
#define OFF_MUZ    (OFF_MU2 + (long long)KK*100)
#define OFF_LOGITS (OFF_MUZ + (long long)KK*EMB)
#define OFF_BETA   (OFF_LOGITS + (long long)KK*VV)
#define OFF_SPM    (OFF_BETA + (long long)KK*VV)
#define OFF_SLV    (OFF_SPM + 4)
#define OFF_SZ     (OFF_SLV + 4)
#define OFF_ST     (OFF_SZ + 4)
#define SCRATCH_FLOATS (OFF_ST + 8)

__device__ float g_scratch[SCRATCH_FLOATS];

// ---------------- fp16 planes (words): A hi, A lo, B hi ----------------------
#define WA 51249152LL           // NB * KPW
#define WB 25624576LL           // E1 * KPW
#define W_AH 0LL
#define W_AL (W_AH + WA)
#define W_BH (W_AL + WA)

__device__ __align__(16) uint32_t g_bf[2*WA + WB];

__device__ __forceinline__ float softplusf(float x) {
    return fmaxf(x, 0.0f) + log1pf(expf(-fabsf(x)));
}

__device__ __forceinline__ uint32_t pk_h2(__half lo, __half hi) {
    return ((uint32_t)__half_as_ushort(hi) << 16) | __half_as_ushort(lo);
}

__device__ __forceinline__ uint32_t pk_bf16(float lo, float hi) {
    uint32_t r;
    asm("cvt.rn.bf16x2.f32 %0, %1, %2;" : "=r"(r) : "f"(hi), "f"(lo));
    return r;
}

__device__ __forceinline__ void mma_f16(float* d,
                                        uint32_t a0, uint32_t a1, uint32_t a2, uint32_t a3,
                                        uint32_t b0, uint32_t b1)
{
    asm volatile(
        "mma.sync.aligned.m16n8k16.row.col.f32.f16.f16.f32 "
        "{%0,%1,%2,%3},{%4,%5,%6,%7},{%8,%9},{%0,%1,%2,%3};"
        : "+f"(d[0]), "+f"(d[1]), "+f"(d[2]), "+f"(d[3])
        : "r"(a0), "r"(a1), "r"(a2), "r"(a3), "r"(b0), "r"(b1));
}

__device__ __forceinline__ void mma_bf16(float* d,
                                         uint32_t a0, uint32_t a1, uint32_t a2, uint32_t a3,
                                         uint32_t b0, uint32_t b1)
{
    asm volatile(
        "mma.sync.aligned.m16n8k16.row.col.f32.bf16.bf16.f32 "
        "{%0,%1,%2,%3},{%4,%5,%6,%7},{%8,%9},{%0,%1,%2,%3};"
        : "+f"(d[0]), "+f"(d[1]), "+f"(d[2]), "+f"(d[3])
        : "r"(a0), "r"(a1), "r"(a2), "r"(a3), "r"(b0), "r"(b1));
}

__device__ __forceinline__ void ldsm_x4(uint32_t& r0, uint32_t& r1, uint32_t& r2,
                                        uint32_t& r3, uint32_t addr)
{
    asm volatile("ldmatrix.sync.aligned.m8n8.x4.shared.b16 {%0,%1,%2,%3}, [%4];"
                 : "=r"(r0), "=r"(r1), "=r"(r2), "=r"(r3) : "r"(addr));
}

// =============================================================================
// Pre-pass: A=input -> two fp16 digit planes (exact split); B=en1_W -> one
// fp16 plane (rn). Rows padded to KP with zeros.
// =============================================================================
__global__ void __launch_bounds__(256)
split_fp16(const float* __restrict__ A, const float* __restrict__ B)
{
    const int b = blockIdx.x, tid = threadIdx.x;
    if (b < NB) {
        const float* src = A + (size_t)b * VV;
        uint32_t* h = g_bf + W_AH + (size_t)b * KPW;
        uint32_t* l = g_bf + W_AL + (size_t)b * KPW;
        for (int i = tid; i < VV / 4; i += 256) {
            float4 v = *reinterpret_cast<const float4*>(src + i * 4);
            __half hx = __float2half_rn(v.x), hy = __float2half_rn(v.y);
            __half hz = __float2half_rn(v.z), hw = __float2half_rn(v.w);
            h[2*i]     = pk_h2(hx, hy);
            h[2*i + 1] = pk_h2(hz, hw);
            l[2*i]     = pk_h2(__float2half_rn(v.x - __half2float(hx)),
                               __float2half_rn(v.y - __half2float(hy)));
            l[2*i + 1] = pk_h2(__float2half_rn(v.z - __half2float(hz)),
                               __float2half_rn(v.w - __half2float(hw)));
        }
        if (tid < KPW - VV/2) {
            h[VV/2 + tid] = 0u;
            l[VV/2 + tid] = 0u;
        }
    } else {
        int r = b - NB;
        const float* src = B + (size_t)r * VV;
        uint32_t* h = g_bf + W_BH + (size_t)r * KPW;
        for (int i = tid; i < VV / 4; i += 256) {
            float4 v = *reinterpret_cast<const float4*>(src + i * 4);
            h[2*i]     = pk_h2(__float2half_rn(v.x), __float2half_rn(v.y));
            h[2*i + 1] = pk_h2(__float2half_rn(v.z), __float2half_rn(v.w));
        }
        if (tid < KPW - VV/2) h[VV/2 + tid] = 0u;
    }
}

// =============================================================================
// GEMM1: en1 = softplus(input @ en1_W^T + b), 2xfp16 (A 2-digit, B 1-digit).
// Block tile 128x128, BK=32, 256 threads (8 warps, 32x64 warp tiles),
// grid (8,16)=128 CTAs. 3-stage cp.async + ldmatrix.
// Stage (bytes): Ah[128x80] @0, Al @10240, Bh[128x80] @20480. STG=30720.
// =============================================================================
#define STG    30720
#define G1_SMEM (3 * STG)          // 92160 B

__global__ void __launch_bounds__(256, 1)
gemm1_fp16(const float* __restrict__ bias, float* __restrict__ C)
{
    extern __shared__ __align__(16) char sm[];
    const uint32_t sb32 = (uint32_t)__cvta_generic_to_shared(sm);
    const int tid = threadIdx.x;
    const int lane = tid & 31, warp = tid >> 5;
    const int gid = lane >> 2, tig = lane & 3;
    const int wm = warp >> 1, wn = warp & 1;           // 4 x 2 warps, 32x64 tiles
    const int m0 = blockIdx.y * 128, n0 = blockIdx.x * 128;

    float acc[2][8][4];
#pragma unroll
    for (int i = 0; i < 2; i++)
#pragma unroll
        for (int j = 0; j < 8; j++)
#pragma unroll
            for (int l = 0; l < 4; l++) acc[i][j][l] = 0.0f;

    // ---- cp.async assignments: 6 x 16B chunks per thread ----
    const uint32_t* gsrc[6];
    uint32_t sdst[6];
#pragma unroll
    for (int i = 0; i < 4; i++) {          // A: 2 planes x 128 rows x 4 parts
        int idx = tid + i * 256;
        int p = idx >> 9, r = (idx >> 2) & 127, part = idx & 3;
        gsrc[i] = g_bf + (p ? W_AL : W_AH) + (size_t)(m0 + r) * KPW + part * 4;
        sdst[i] = sb32 + (uint32_t)(p * 10240 + r * 80 + part * 16);
    }
#pragma unroll
    for (int i = 0; i < 2; i++) {          // B: 1 plane x 128 rows x 4 parts
        int idx = tid + i * 256;           // 0..511
        int r = idx >> 2, part = idx & 3;
        gsrc[4 + i] = g_bf + W_BH + (size_t)(n0 + r) * KPW + part * 4;
        sdst[4 + i] = sb32 + (uint32_t)(20480 + r * 80 + part * 16);
    }

    auto issue = [&](int t) {
        const uint32_t boff = (uint32_t)(t % 3) * STG;
        const size_t k = (size_t)t * 16;
#pragma unroll
        for (int i = 0; i < 6; i++)
            asm volatile("cp.async.cg.shared.global [%0], [%1], 16;"
                         :: "r"(sdst[i] + boff), "l"(gsrc[i] + k) : "memory");
        asm volatile("cp.async.commit_group;" ::: "memory");
    };

    const int lr = (lane & 7) + ((lane >> 3) & 1) * 8;
    const int kb = ((lane >> 4) & 1) * 16;
    const uint32_t aoff = (uint32_t)((wm * 32 + lr) * 80 + kb);
    const uint32_t boff2 = (uint32_t)(20480 + (wn * 64 + lr) * 80 + kb);

    issue(0);
    issue(1);

    for (int t = 0; t < G1NT; t++) {
        if (t == G1NT - 1) asm volatile("cp.async.wait_group 0;" ::: "memory");
        else               asm volatile("cp.async.wait_group 1;" ::: "memory");
        __syncthreads();
        if (t + 2 < G1NT) issue(t + 2);

        const uint32_t st = sb32 + (uint32_t)(t % 3) * STG;
#pragma unroll
        for (int kkw = 0; kkw < 2; kkw++) {
            const uint32_t ka = st + kkw * 32;
            uint32_t ah[2][4], al[2][4], bq[4][4];
#pragma unroll
            for (int ms = 0; ms < 2; ms++) {
                ldsm_x4(ah[ms][0], ah[ms][1], ah[ms][2], ah[ms][3],
                        ka + aoff + ms * 1280);
                ldsm_x4(al[ms][0], al[ms][1], al[ms][2], al[ms][3],
                        ka + aoff + ms * 1280 + 10240);
            }
#pragma unroll
            for (int pr = 0; pr < 4; pr++)
                ldsm_x4(bq[pr][0], bq[pr][1], bq[pr][2], bq[pr][3],
                        ka + boff2 + pr * 1280);
#pragma unroll
            for (int ms = 0; ms < 2; ms++)
#pragma unroll
                for (int pr = 0; pr < 4; pr++)
#pragma unroll
                    for (int j = 0; j < 2; j++) {
                        int ns = pr * 2 + j;
                        mma_f16(acc[ms][ns], ah[ms][0], ah[ms][1], ah[ms][2], ah[ms][3],
                                bq[pr][j], bq[pr][j + 2]);
                        mma_f16(acc[ms][ns], al[ms][0], al[ms][1], al[ms][2], al[ms][3],
                                bq[pr][j], bq[pr][j + 2]);
                    }
        }
    }

    // epilogue
#pragma unroll
    for (int ms = 0; ms < 2; ms++) {
        const int r0 = m0 + wm * 32 + ms * 16 + gid;
#pragma unroll
        for (int ns = 0; ns < 8; ns++) {
            const int c0 = n0 + wn * 64 + ns * 8 + 2 * tig;
            const float bv0 = bias[c0], bv1 = bias[c0 + 1];
            C[(size_t)r0 * E1 + c0]           = softplusf(acc[ms][ns][0] + bv0);
            C[(size_t)r0 * E1 + c0 + 1]       = softplusf(acc[ms][ns][1] + bv1);
            C[(size_t)(r0 + 8) * E1 + c0]     = softplusf(acc[ms][ns][2] + bv0);
            C[(size_t)(r0 + 8) * E1 + c0 + 1] = softplusf(acc[ms][ns][3] + bv1);
        }
    }
}

// ============================ bf16x3 NT GEMM (en2 + logits) ==================
#define NTB_SMEM (2 * 10240 * 4)

template<bool SP, bool HB, bool CHKMN>
__global__ void __launch_bounds__(512, 1)
gemm_nt_bf16x3(const float* __restrict__ A, const float* __restrict__ B,
               const float* __restrict__ bias, float* __restrict__ C,
               int M, int N, int K)
{
    extern __shared__ __align__(16) uint32_t sw[];
    const int tid = threadIdx.x;
    const int lane = tid & 31, warp = tid >> 5;
    const int gid = lane >> 2, tig = lane & 3;
    const int wm = warp >> 2, wn = warp & 3;
    const int m0 = blockIdx.y * 128, n0 = blockIdx.x * 128;
    const int nt = (K + 31) / 32;

    float acc[2][4][4];
#pragma unroll
    for (int i = 0; i < 2; i++)
#pragma unroll
        for (int j = 0; j < 4; j++)
#pragma unroll
            for (int l = 0; l < 4; l++) acc[i][j][l] = 0.0f;

    const int srow = tid >> 3;
    const int sq   = tid & 7;
    float4 stA[2], stB[2];

    auto load_tile = [&](int t) {
        const int gk = t * 32 + sq * 4;
#pragma unroll
        for (int l = 0; l < 2; l++) {
            int r = srow + l * 64;
            {
                int gm = m0 + r;
                float4 v = make_float4(0.f, 0.f, 0.f, 0.f);
                if (((!CHKMN) || gm < M)) {
                    if (gk + 3 < K) v = *reinterpret_cast<const float4*>(A + (size_t)gm * K + gk);
                    else if (gk < K) {
                        const float* p = A + (size_t)gm * K;
                        v.x = p[gk];
                        if (gk + 1 < K) v.y = p[gk + 1];
                        if (gk + 2 < K) v.z = p[gk + 2];
                    }
                }
                stA[l] = v;
            }
            {
                int gn = n0 + r;
                float4 v = make_float4(0.f, 0.f, 0.f, 0.f);
                if (((!CHKMN) || gn < N)) {
                    if (gk + 3 < K) v = *reinterpret_cast<const float4*>(B + (size_t)gn * K + gk);
                    else if (gk < K) {
                        const float* p = B + (size_t)gn * K;
                        v.x = p[gk];
                        if (gk + 1 < K) v.y = p[gk + 1];
                        if (gk + 2 < K) v.z = p[gk + 2];
                    }
                }
                stB[l] = v;
            }
        }
    };

    auto store_tile = [&](uint32_t* buf) {
#pragma unroll
        for (int l = 0; l < 2; l++) {
            int r = srow + l * 64;
            uint32_t w = (uint32_t)(r * 20 + sq * 2);
            {
                float4 v = stA[l];
                __nv_bfloat16 hx = __float2bfloat16_rn(v.x), hy = __float2bfloat16_rn(v.y);
                __nv_bfloat16 hz = __float2bfloat16_rn(v.z), hw = __float2bfloat16_rn(v.w);
                buf[w]     = ((uint32_t)__bfloat16_as_ushort(hy) << 16) | __bfloat16_as_ushort(hx);
                buf[w + 1] = ((uint32_t)__bfloat16_as_ushort(hw) << 16) | __bfloat16_as_ushort(hz);
                buf[w + 2560]     = pk_bf16(v.x - __bfloat162float(hx), v.y - __bfloat162float(hy));
                buf[w + 2560 + 1] = pk_bf16(v.z - __bfloat162float(hz), v.w - __bfloat162float(hw));
            }
            {
                float4 v = stB[l];
                __nv_bfloat16 hx = __float2bfloat16_rn(v.x), hy = __float2bfloat16_rn(v.y);
                __nv_bfloat16 hz = __float2bfloat16_rn(v.z), hw = __float2bfloat16_rn(v.w);
                buf[w + 5120]     = ((uint32_t)__bfloat16_as_ushort(hy) << 16) | __bfloat16_as_ushort(hx);
                buf[w + 5120 + 1] = ((uint32_t)__bfloat16_as_ushort(hw) << 16) | __bfloat16_as_ushort(hz);
                buf[w + 7680]     = pk_bf16(v.x - __bfloat162float(hx), v.y - __bfloat162float(hy));
                buf[w + 7680 + 1] = pk_bf16(v.z - __bfloat162float(hz), v.w - __bfloat162float(hw));
            }
        }
    };

    load_tile(0);
    store_tile(sw);
    __syncthreads();

    for (int t = 0; t < nt; t++) {
        const int b = t & 1;
        uint32_t* bb = sw + b * 10240;
        if (t + 1 < nt) load_tile(t + 1);

#pragma unroll
        for (int kkw = 0; kkw < 16; kkw += 8) {
            uint32_t ah[2][4], al[2][4], bh[4][2], bl[4][2];
#pragma unroll
            for (int ms = 0; ms < 2; ms++) {
                int base = (wm * 32 + ms * 16 + gid) * 20 + kkw + tig;
                ah[ms][0] = bb[base];       ah[ms][1] = bb[base + 160];
                ah[ms][2] = bb[base + 4];   ah[ms][3] = bb[base + 164];
                al[ms][0] = bb[base + 2560];       al[ms][1] = bb[base + 2560 + 160];
                al[ms][2] = bb[base + 2560 + 4];   al[ms][3] = bb[base + 2560 + 164];
            }
#pragma unroll
            for (int ns = 0; ns < 4; ns++) {
                int base = 5120 + (wn * 32 + ns * 8 + gid) * 20 + kkw + tig;
                bh[ns][0] = bb[base];       bh[ns][1] = bb[base + 4];
                bl[ns][0] = bb[base + 2560]; bl[ns][1] = bb[base + 2560 + 4];
            }
#pragma unroll
            for (int ms = 0; ms < 2; ms++)
#pragma unroll
                for (int ns = 0; ns < 4; ns++) {
                    mma_bf16(acc[ms][ns], ah[ms][0], ah[ms][1], ah[ms][2], ah[ms][3],
                             bh[ns][0], bh[ns][1]);
                    mma_bf16(acc[ms][ns], ah[ms][0], ah[ms][1], ah[ms][2], ah[ms][3],
                             bl[ns][0], bl[ns][1]);
                    mma_bf16(acc[ms][ns], al[ms][0], al[ms][1], al[ms][2], al[ms][3],
                             bh[ns][0], bh[ns][1]);
                }
        }

        if (t + 1 < nt) store_tile(sw + (b ^ 1) * 10240);
        __syncthreads();
    }

#pragma unroll
    for (int ms = 0; ms < 2; ms++) {
        int r0 = m0 + wm * 32 + ms * 16 + gid;
#pragma unroll
        for (int ns = 0; ns < 4; ns++) {
            int c0 = n0 + wn * 32 + ns * 8 + 2 * tig;
            float bv0 = 0.f, bv1 = 0.f;
            if (HB) { bv0 = bias[c0]; bv1 = bias[c0 + 1]; }
            float v00 = acc[ms][ns][0] + bv0;
            float v01 = acc[ms][ns][1] + bv1;
            float v10 = acc[ms][ns][2] + bv0;
            float v11 = acc[ms][ns][3] + bv1;
            if (SP) { v00 = softplusf(v00); v01 = softplusf(v01);
                      v10 = softplusf(v10); v11 = softplusf(v11); }
            if (!CHKMN) {
                C[(size_t)r0 * N + c0]           = v00;
                C[(size_t)r0 * N + c0 + 1]       = v01;
                C[(size_t)(r0 + 8) * N + c0]     = v10;
                C[(size_t)(r0 + 8) * N + c0 + 1] = v11;
            } else {
                if (r0 < M) {
                    if (c0 < N)     C[(size_t)r0 * N + c0]     = v00;
                    if (c0 + 1 < N) C[(size_t)r0 * N + c0 + 1] = v01;
                }
                if (r0 + 8 < M) {
                    if (c0 < N)     C[(size_t)(r0 + 8) * N + c0]     = v10;
                    if (c0 + 1 < N) C[(size_t)(r0 + 8) * N + c0 + 1] = v11;
                }
            }
        }
    }
}

// ============================ tf32 recon =====================================
__device__ __forceinline__ unsigned tf32_rna(float x) {
    unsigned r;
    asm("cvt.rna.tf32.f32 %0, %1;" : "=r"(r) : "f"(x));
    return r;
}

__device__ __forceinline__ void mma_tf32(float* d,
                                         unsigned a0, unsigned a1, unsigned a2, unsigned a3,
                                         unsigned b0, unsigned b1)
{
    asm volatile(
        "mma.sync.aligned.m16n8k8.row.col.f32.tf32.tf32.f32 "
        "{%0,%1,%2,%3},{%4,%5,%6,%7},{%8,%9},{%0,%1,%2,%3};"
        : "+f"(d[0]), "+f"(d[1]), "+f"(d[2]), "+f"(d[3])
        : "r"(a0), "r"(a1), "r"(a2), "r"(a3), "r"(b0), "r"(b1));
}

__global__ void __launch_bounds__(256, 2)
recon_tf32(const float* __restrict__ A, const float* __restrict__ B,
           float* __restrict__ C)
{
    __shared__ float Ah[128][20];
    __shared__ float Bh[16][136];
    const int tid = threadIdx.x;
    const int lane = tid & 31, warp = tid >> 5;
    const int gid = lane >> 2, tig = lane & 3;
    const int wm = warp >> 1, wn = warp & 1;
    const int m0 = blockIdx.y * 128;
    const int n0 = blockIdx.x * 128;

    float acc[2][8][4];
#pragma unroll
    for (int i = 0; i < 2; i++)
#pragma unroll
        for (int j = 0; j < 8; j++)
#pragma unroll
            for (int l = 0; l < 4; l++) acc[i][j][l] = 0.0f;

    for (int k0 = 0; k0 < KK; k0 += 16) {
#pragma unroll
        for (int l = 0; l < 2; l++) {
            int idx = tid + l * 256;
            int row = idx >> 2, kq = (idx & 3) * 4;
            int gk = k0 + kq;
            float4 v = make_float4(0.f, 0.f, 0.f, 0.f);
            if (gk + 3 < KK)
                v = *reinterpret_cast<const float4*>(A + (size_t)(m0 + row) * KK + gk);
            Ah[row][kq + 0] = __uint_as_float(tf32_rna(v.x));
            Ah[row][kq + 1] = __uint_as_float(tf32_rna(v.y));
            Ah[row][kq + 2] = __uint_as_float(tf32_rna(v.z));
            Ah[row][kq + 3] = __uint_as_float(tf32_rna(v.w));
        }
#pragma unroll
        for (int l = 0; l < 2; l++) {
            int idx = tid + l * 256;
            int kk = idx >> 5, nc = (idx & 31) * 4;
            int gk = k0 + kk, gn = n0 + nc;
            float4 v = make_float4(0.f, 0.f, 0.f, 0.f);
            if (gk < KK && gn + 3 < VV)
                v = *reinterpret_cast<const float4*>(B + (size_t)gk * VV + gn);
            Bh[kk][nc + 0] = __uint_as_float(tf32_rna(v.x));
            Bh[kk][nc + 1] = __uint_as_float(tf32_rna(v.y));
            Bh[kk][nc + 2] = __uint_as_float(tf32_rna(v.z));
            Bh[kk][nc + 3] = __uint_as_float(tf32_rna(v.w));
        }
        __syncthreads();

#pragma unroll
        for (int kk = 0; kk < 16; kk += 8) {
            unsigned a[2][4], b[8][2];
#pragma unroll
            for (int ms = 0; ms < 2; ms++) {
                int r = wm * 32 + ms * 16 + gid;
                a[ms][0] = __float_as_uint(Ah[r][kk + tig]);
                a[ms][1] = __float_as_uint(Ah[r + 8][kk + tig]);
                a[ms][2] = __float_as_uint(Ah[r][kk + tig + 4]);
                a[ms][3] = __float_as_uint(Ah[r + 8][kk + tig + 4]);
            }
#pragma unroll
            for (int ns = 0; ns < 8; ns++) {
                int n = wn * 64 + ns * 8 + gid;
                b[ns][0] = __float_as_uint(Bh[kk + tig][n]);
                b[ns][1] = __float_as_uint(Bh[kk + tig + 4][n]);
            }
#pragma unroll
            for (int ms = 0; ms < 2; ms++)
#pragma unroll
                for (int ns = 0; ns < 8; ns++)
                    mma_tf32(acc[ms][ns], a[ms][0], a[ms][1], a[ms][2], a[ms][3],
                             b[ns][0], b[ns][1]);
        }
        __syncthreads();
    }

#pragma unroll
    for (int ms = 0; ms < 2; ms++) {
        int r0 = m0 + wm * 32 + ms * 16 + gid;
#pragma unroll
        for (int ns = 0; ns < 8; ns++) {
            int c0 = n0 + wn * 64 + ns * 8 + 2 * tig;
            if (c0 < VV) {
                C[(size_t)r0 * VV + c0]       = acc[ms][ns][0];
                C[(size_t)(r0 + 8) * VV + c0] = acc[ms][ns][2];
            }
            if (c0 + 1 < VV) {
                C[(size_t)r0 * VV + c0 + 1]       = acc[ms][ns][1];
                C[(size_t)(r0 + 8) * VV + c0 + 1] = acc[ms][ns][3];
            }
        }
    }
}

// ---------------- mean / logvar heads ---------------------------------------
__global__ void meanlogvar_kernel(const float* __restrict__ en2,
                                  const float* __restrict__ mW, const float* __restrict__ mb,
                                  const float* __restrict__ lW, const float* __restrict__ lb,
                                  float* __restrict__ pm, float* __restrict__ lv)
{
    int t = blockIdx.x * blockDim.x + threadIdx.x;
    if (t >= NB * 4) return;
    int n = t >> 2, j = t & 3;
    const float* w = (j < 2) ? (mW + j * E2) : (lW + (j - 2) * E2);
    const float* x = en2 + (size_t)n * E2;
    float s = 0.f;
    for (int i = 0; i < E2; i += 4) {
        float4 xa = *reinterpret_cast<const float4*>(x + i);
        float4 wa = *reinterpret_cast<const float4*>(w + i);
        s += xa.x * wa.x + xa.y * wa.y + xa.z * wa.z + xa.w * wa.w;
    }
    if (j < 2) pm[n * 2 + j] = s + mb[j];
    else       lv[n * 2 + (j - 2)] = s + lb[j - 2];
}

// ---------------- column stats of (R x 2) -----------------------------------
__global__ void colstats_kernel(const float* __restrict__ X, int R, float* __restrict__ out)
{
    __shared__ float ss[256], s2[256];
    int c = blockIdx.x, tid = threadIdx.x;
    float s = 0.f, q = 0.f;
    for (int r = tid; r < R; r += 256) {
        float x = X[r * 2 + c];
        s += x; q += x * x;
    }
    ss[tid] = s; s2[tid] = q;
    __syncthreads();
    for (int st = 128; st > 0; st >>= 1) {
        if (tid < st) { ss[tid] += ss[tid + st]; s2[tid] += s2[tid + st]; }
        __syncthreads();
    }
    if (tid == 0) {
        float m = ss[0] / R;
        out[c] = m;
        out[2 + c] = s2[0] / R - m * m;
    }
}

// ---------------- z ----------------------------------------------------------
__global__ void z_kernel(const float* __restrict__ pm, const float* __restrict__ lv,
                         const float* __restrict__ spm, const float* __restrict__ slv,
                         const float* __restrict__ gm, const float* __restrict__ bm,
                         const float* __restrict__ gl, const float* __restrict__ bl,
                         const float* __restrict__ eps,
                         float* __restrict__ gz, float* __restrict__ outz)
{
    int idx = blockIdx.x * 256 + threadIdx.x;
    if (idx >= NB * CC) return;
    int c = idx & 1;
    float pmb = gm[c] * (pm[idx] - spm[c]) * rsqrtf(spm[2 + c] + 1e-5f) + bm[c];
    float lvb = gl[c] * (lv[idx] - slv[c]) * rsqrtf(slv[2 + c] + 1e-5f) + bl[c];
    float z = pmb + sqrtf(expf(lvb)) * eps[idx];
    gz[idx] = z;
    outz[idx] = z;
}

// ---------------- BN apply ---------------------------------------------------
__global__ void bn_apply_kernel(const float* __restrict__ X, const float* __restrict__ stats,
                                const float* __restrict__ g, const float* __restrict__ b,
                                int total, float* __restrict__ o1, float* __restrict__ o2)
{
    int idx = blockIdx.x * 256 + threadIdx.x;
    if (idx >= total) return;
    int c = idx & 1;
    float y = g[c] * (X[idx] - stats[c]) * rsqrtf(stats[2 + c] + 1e-5f) + b[c];
    o1[idx] = y;
    o2[idx] = y;
}

// ---------------- theta ------------------------------------------------------
__global__ void theta_kernel(const float* __restrict__ zx, const float* __restrict__ zc,
                             float* __restrict__ gtheta, float* __restrict__ otheta)
{
    __shared__ float sz[KK * 2];
    __shared__ float red[256];
    int n = blockIdx.x, tid = threadIdx.x;
    for (int i = tid; i < KK * 2; i += 256) sz[i] = zc[i];
    __syncthreads();
    float x0 = zx[n * 2], x1 = zx[n * 2 + 1];
    float l = -FLT_MAX;
    if (tid < KK) {
        float dx = x0 - sz[tid * 2];
        float dy = x1 - sz[tid * 2 + 1];
        l = -0.5f * (dx * dx + dy * dy);
    }
    red[tid] = l;
    __syncthreads();
    for (int st = 128; st > 0; st >>= 1) {
        if (tid < st) red[tid] = fmaxf(red[tid], red[tid + st]);
        __syncthreads();
    }
    float mx = red[0];
    __syncthreads();
    float e = (tid < KK) ? expf(l - mx) : 0.f;
    red[tid] = e;
    __syncthreads();
    for (int st = 128; st > 0; st >>= 1) {
        if (tid < st) red[tid] += red[tid + st];
        __syncthreads();
    }
    float inv = 1.f / red[0];
    if (tid < KK) {
        float th = e * inv;
        gtheta[(size_t)n * KK + tid] = th;
        otheta[(size_t)n * KK + tid] = th;
    }
}

// ---------------- decoder MLP ------------------------------------------------
__global__ void mu1_kernel(const float* __restrict__ zc, const float* __restrict__ W,
                           const float* __restrict__ b, float* __restrict__ out)
{
    int t = blockIdx.x * 256 + threadIdx.x;
    if (t >= KK * 100) return;
    int k = t / 100, j = t % 100;
    float v = zc[k * 2] * W[j * 2] + zc[k * 2 + 1] * W[j * 2 + 1] + b[j];
    out[t] = softplusf(v);
}

__global__ void mu2_kernel(const float* __restrict__ mu1, const float* __restrict__ W,
                           const float* __restrict__ b, float* __restrict__ out)
{
    __shared__ float row[100];
    int k = blockIdx.x, tid = threadIdx.x;
    if (tid < 100) row[tid] = mu1[k * 100 + tid];
    __syncthreads();
    if (tid < 100) {
        const float* w = W + tid * 100;
        float s = b[tid];
        for (int i = 0; i < 100; i++) s += row[i] * w[i];
        out[k * 100 + tid] = softplusf(s);
    }
}

__global__ void muz_kernel(const float* __restrict__ mu2, const float* __restrict__ W,
                           const float* __restrict__ b, float* __restrict__ out)
{
    __shared__ float row[100];
    int k = blockIdx.x, tid = threadIdx.x;
    if (tid < 100) row[tid] = mu2[k * 100 + tid];
    __syncthreads();
    for (int j = tid; j < EMB; j += 128) {
        const float* w = W + j * 100;
        float s = b[j];
        for (int i = 0; i < 100; i++) s += row[i] * w[i];
        out[k * EMB + j] = s;
    }
}

// ---------------- beta -------------------------------------------------------
__global__ void __launch_bounds__(1024)
beta_kernel(const float* __restrict__ logits, const float* __restrict__ bbias,
            const float* __restrict__ gdec, const float* __restrict__ bdec,
            float* __restrict__ beta)
{
    __shared__ float red[1024];
    __shared__ float red2[1024];
    const int k = blockIdx.x, tid = threadIdx.x;
    const float* row = logits + (size_t)k * VV;
    const float* bb  = bbias + (size_t)k * VV;

    float s = 0.f, q = 0.f;
    for (int v = tid; v < VV; v += 1024) { float x = row[v]; s += x; q += x * x; }
    red[tid] = s; red2[tid] = q;
    __syncthreads();
    for (int st = 512; st > 0; st >>= 1) {
        if (tid < st) { red[tid] += red[tid + st]; red2[tid] += red2[tid + st]; }
        __syncthreads();
    }
    float mean = red[0] / VV;
    float var  = red2[0] / VV - mean * mean;
    float scale = gdec[k] * rsqrtf(var + 1e-5f);
    float shift = bdec[k] - mean * scale;
    __syncthreads();

    float mx = -FLT_MAX;
    for (int v = tid; v < VV; v += 1024) {
        float y = row[v] * scale + shift + bb[v];
        mx = fmaxf(mx, y);
    }
    red[tid] = mx;
    __syncthreads();
    for (int st = 512; st > 0; st >>= 1) {
        if (tid < st) red[tid] = fmaxf(red[tid], red[tid + st]);
        __syncthreads();
    }
    mx = red[0];
    __syncthreads();

    float se = 0.f;
    for (int v = tid; v < VV; v += 1024) {
        float y = row[v] * scale + shift + bb[v];
        se += expf(y - mx);
    }
    red[tid] = se;
    __syncthreads();
    for (int st = 512; st > 0; st >>= 1) {
        if (tid < st) red[tid] += red[tid + st];
        __syncthreads();
    }
    float inv = 1.f / red[0];

    for (int v = tid; v < VV; v += 1024) {
        float y = row[v] * scale + shift + bb[v];
        beta[(size_t)k * VV + v] = expf(y - mx) * inv;
    }
}

// ---------------- launch -----------------------------------------------------
extern "C" void kernel_launch(void* const* d_in, const int* in_sizes, int n_in,
                              void* d_out, int out_size)
{
    const float* input_   = (const float*)d_in[0];
    const float* eps      = (const float*)d_in[2];
    const float* en1_W    = (const float*)d_in[3];
    const float* en1_b    = (const float*)d_in[4];
    const float* en2_W    = (const float*)d_in[5];
    const float* en2_b    = (const float*)d_in[6];
    const float* mean_W   = (const float*)d_in[7];
    const float* mean_b   = (const float*)d_in[8];
    const float* logvar_W = (const float*)d_in[9];
    const float* logvar_b = (const float*)d_in[10];
    const float* mu1_W    = (const float*)d_in[11];
    const float* mu1_b    = (const float*)d_in[12];
    const float* mu2_W    = (const float*)d_in[13];
    const float* mu2_b    = (const float*)d_in[14];
    const float* mu_W     = (const float*)d_in[15];
    const float* mu_b     = (const float*)d_in[16];
    const float* topics   = (const float*)d_in[17];
    const float* bbias    = (const float*)d_in[18];
    const float* emb      = (const float*)d_in[19];
    const float* g_mean   = (const float*)d_in[20];
    const float* b_mean   = (const float*)d_in[21];
    const float* g_logvar = (const float*)d_in[22];
    const float* b_logvar = (const float*)d_in[23];
    const float* g_x      = (const float*)d_in[24];
    const float* b_x      = (const float*)d_in[25];
    const float* g_phi    = (const float*)d_in[26];
    const float* b_phi    = (const float*)d_in[27];
    const float* g_dec    = (const float*)d_in[28];
    const float* b_dec    = (const float*)d_in[29];

    float* out = (float*)d_out;
    float* out_z     = out;
    float* out_recon = out + (long long)NB * CC;
    float* out_zx    = out_recon + (long long)NB * VV;
    float* out_zc    = out_zx + (long long)NB * CC;
    float* out_theta = out_zc + (long long)KK * CC;

    void* sp = nullptr;
    cudaGetSymbolAddress(&sp, g_scratch);
    float* S = (float*)sp;
    float* s_en1    = S + OFF_EN1;
    float* s_en2    = S + OFF_EN2;
    float* s_pm     = S + OFF_PM;
    float* s_lv     = S + OFF_LV;
    float* s_z      = S + OFF_Z;
    float* s_zx     = S + OFF_ZX;
    float* s_zc     = S + OFF_ZC;
    float* s_theta  = S + OFF_THETA;
    float* s_mu1    = S + OFF_MU1;
    float* s_mu2    = S + OFF_MU2;
    float* s_muz    = S + OFF_MUZ;
    float* s_logits = S + OFF_LOGITS;
    float* s_beta   = S + OFF_BETA;
    float* st_pm    = S + OFF_SPM;
    float* st_lv    = S + OFF_SLV;
    float* st_z     = S + OFF_SZ;
    float* st_t     = S + OFF_ST;

    cudaFuncSetAttribute(gemm1_fp16, cudaFuncAttributeMaxDynamicSharedMemorySize, G1_SMEM);
    cudaFuncSetAttribute(gemm_nt_bf16x3<true, true, false>,
                         cudaFuncAttributeMaxDynamicSharedMemorySize, NTB_SMEM);
    cudaFuncSetAttribute(gemm_nt_bf16x3<false, false, true>,
                         cudaFuncAttributeMaxDynamicSharedMemorySize, NTB_SMEM);

    // 0) pre-split: A -> 2 fp16 digit planes, B -> 1 fp16 plane
    split_fp16<<<NB + E1, 256>>>(input_, en1_W);

    // 1-4) decoder-side small kernels
    colstats_kernel<<<2, 256>>>(topics, KK, st_t);
    bn_apply_kernel<<<(KK * CC + 255) / 256, 256>>>(topics, st_t, g_phi, b_phi, KK * CC, s_zc, out_zc);
    mu1_kernel<<<(KK * 100 + 255) / 256, 256>>>(s_zc, mu1_W, mu1_b, s_mu1);
    mu2_kernel<<<KK, 128>>>(s_mu1, mu2_W, mu2_b, s_mu2);

    // 5) en1 = softplus(input @ en1_W^T + b) — 2xfp16
    gemm1_fp16<<<dim3(E1 / 128, NB / 128), 256, G1_SMEM>>>(en1_b, s_en1);

    // 6) muz
    muz_kernel<<<KK, 128>>>(s_mu2, mu_W, mu_b, s_muz);

    // 7) en2 — bf16x3
    gemm_nt_bf16x3<true, true, false><<<dim3(E2 / 128, NB / 128), 512, NTB_SMEM>>>(
        s_en1, en2_W, en2_b, s_en2, NB, E2, E1);

    // 8) heads
    meanlogvar_kernel<<<(NB * 4 + 255) / 256, 256>>>(
        s_en2, mean_W, mean_b, logvar_W, logvar_b, s_pm, s_lv);

    // 9-11) BN stats + z
    colstats_kernel<<<2, 256>>>(s_pm, NB, st_pm);
    colstats_kernel<<<2, 256>>>(s_lv, NB, st_lv);
    z_kernel<<<(NB * CC + 255) / 256, 256>>>(
        s_pm, s_lv, st_pm, st_lv, g_mean, b_mean, g_logvar, b_logvar, eps, s_z, out_z);

    // 12-13) zx
    colstats_kernel<<<2, 256>>>(s_z, NB, st_z);
    bn_apply_kernel<<<(NB * CC + 255) / 256, 256>>>(s_z, st_z, g_x, b_x, NB * CC, s_zx, out_zx);

    // 14) theta
    theta_kernel<<<NB, 256>>>(s_zx, s_zc, s_theta, out_theta);

    // 15) logits = mu_z @ emb^T — bf16x3
    gemm_nt_bf16x3<false, false, true><<<dim3((VV + 127) / 128, (KK + 127) / 128), 512, NTB_SMEM>>>(
        s_muz, emb, nullptr, s_logits, KK, VV, EMB);

    // 16) beta
    beta_kernel<<<KK, 1024>>>(s_logits, bbias, g_dec, b_dec, s_beta);

    // 17) recon = theta @ beta
    recon_tf32<<<dim3((VV + 127) / 128, NB / 128), 256>>>(s_theta, s_beta, out_recon);

    (void)in_sizes; (void)n_in; (void)out_size;
}

// round 9
// speedup vs baseline: 1.8114x; 1.3801x over previous
#include <cuda_runtime.h>
#include <cuda_bf16.h>
#include <cuda_fp16.h>
#include <math.h>
#include <float.h>
#include <stdint.h>

// ---------------- problem dims ----------------
#define NB   2048
#define VV   50000
#define E1   1024
#define E2   512
#define CC   2
#define KK   200
#define EMB  300

#define KP   50048              // VV padded to multiple of 32
#define KPW  (KP/2)             // 25024 words per row
#define G1NT (KP / 32)          // 1564 k-tiles

// ---------------- float scratch ----------------------------------------------
#define OFF_EN1    0LL
#define OFF_EN2    (OFF_EN1 + (long long)NB*E1)
#define OFF_PM     (OFF_EN2 + (long long)NB*E2)
#define OFF_LV     (OFF_PM + (long long)NB*CC)
#define OFF_Z      (OFF_LV + (long long)NB*CC)
#define OFF_ZX     (OFF_Z + (long long)NB*CC)
#define OFF_ZC     (OFF_ZX + (long long)NB*CC)
#define OFF_THETA  (OFF_ZC + (long long)KK*CC)
#define OFF_MU1    (OFF_THETA + (long long)NB*KK)
#define OFF_MU2    (OFF_MU1 + (long long)KK*100)
#define OFF_MUZ    (OFF_MU2 + (long long)KK*100)
#define OFF_LOGITS (OFF_MUZ + (long long)KK*EMB)
#define OFF_BETA   (OFF_LOGITS + (long long)KK*VV)
#define OFF_SPM    (OFF_BETA + (long long)KK*VV)
#define OFF_SLV    (OFF_SPM + 4)
#define OFF_SZ     (OFF_SLV + 4)
#define OFF_ST     (OFF_SZ + 4)
#define SCRATCH_FLOATS (OFF_ST + 8)

__device__ float g_scratch[SCRATCH_FLOATS];

// ---------------- fp16 planes (words): A hi, B hi -----------------------------
#define WA 51249152LL           // NB * KPW
#define WB 25624576LL           // E1 * KPW
#define W_AH 0LL
#define W_BH (W_AH + WA)

__device__ __align__(16) uint32_t g_bf[WA + WB];

__device__ __forceinline__ float softplusf(float x) {
    return fmaxf(x, 0.0f) + log1pf(expf(-fabsf(x)));
}

__device__ __forceinline__ uint32_t pk_h2(__half lo, __half hi) {
    return ((uint32_t)__half_as_ushort(hi) << 16) | __half_as_ushort(lo);
}

__device__ __forceinline__ uint32_t pk_bf16(float lo, float hi) {
    uint32_t r;
    asm("cvt.rn.bf16x2.f32 %0, %1, %2;" : "=r"(r) : "f"(hi), "f"(lo));
    return r;
}

__device__ __forceinline__ void mma_f16(float* d,
                                        uint32_t a0, uint32_t a1, uint32_t a2, uint32_t a3,
                                        uint32_t b0, uint32_t b1)
{
    asm volatile(
        "mma.sync.aligned.m16n8k16.row.col.f32.f16.f16.f32 "
        "{%0,%1,%2,%3},{%4,%5,%6,%7},{%8,%9},{%0,%1,%2,%3};"
        : "+f"(d[0]), "+f"(d[1]), "+f"(d[2]), "+f"(d[3])
        : "r"(a0), "r"(a1), "r"(a2), "r"(a3), "r"(b0), "r"(b1));
}

__device__ __forceinline__ void mma_bf16(float* d,
                                         uint32_t a0, uint32_t a1, uint32_t a2, uint32_t a3,
                                         uint32_t b0, uint32_t b1)
{
    asm volatile(
        "mma.sync.aligned.m16n8k16.row.col.f32.bf16.bf16.f32 "
        "{%0,%1,%2,%3},{%4,%5,%6,%7},{%8,%9},{%0,%1,%2,%3};"
        : "+f"(d[0]), "+f"(d[1]), "+f"(d[2]), "+f"(d[3])
        : "r"(a0), "r"(a1), "r"(a2), "r"(a3), "r"(b0), "r"(b1));
}

__device__ __forceinline__ void ldsm_x4(uint32_t& r0, uint32_t& r1, uint32_t& r2,
                                        uint32_t& r3, uint32_t addr)
{
    asm volatile("ldmatrix.sync.aligned.m8n8.x4.shared.b16 {%0,%1,%2,%3}, [%4];"
                 : "=r"(r0), "=r"(r1), "=r"(r2), "=r"(r3) : "r"(addr));
}

// =============================================================================
// Pre-pass: A=input -> one fp16 plane; B=en1_W -> one fp16 plane. Zero pad.
// =============================================================================
__global__ void __launch_bounds__(256)
split_fp16(const float* __restrict__ A, const float* __restrict__ B)
{
    const int b = blockIdx.x, tid = threadIdx.x;
    const float* src;
    uint32_t* h;
    if (b < NB) {
        src = A + (size_t)b * VV;
        h = g_bf + W_AH + (size_t)b * KPW;
    } else {
        int r = b - NB;
        src = B + (size_t)r * VV;
        h = g_bf + W_BH + (size_t)r * KPW;
    }
    for (int i = tid; i < VV / 4; i += 256) {
        float4 v = *reinterpret_cast<const float4*>(src + i * 4);
        h[2*i]     = pk_h2(__float2half_rn(v.x), __float2half_rn(v.y));
        h[2*i + 1] = pk_h2(__float2half_rn(v.z), __float2half_rn(v.w));
    }
    if (tid < KPW - VV/2) h[VV/2 + tid] = 0u;
}

// =============================================================================
// GEMM1: en1 = softplus(input @ en1_W^T + b), plain fp16 from pre-split planes.
// Block tile 128x128, BK=32, 256 threads (8 warps, 32x64 warp tiles),
// grid (8,16)=128 CTAs. 3-stage cp.async + ldmatrix.
// Stage (bytes): A[128x80] @0, B[128x80] @10240. STG=20480.
// =============================================================================
#define STG    20480
#define G1_SMEM (3 * STG)          // 61440 B

__global__ void __launch_bounds__(256, 2)
gemm1_fp16(const float* __restrict__ bias, float* __restrict__ C)
{
    extern __shared__ __align__(16) char sm[];
    const uint32_t sb32 = (uint32_t)__cvta_generic_to_shared(sm);
    const int tid = threadIdx.x;
    const int lane = tid & 31, warp = tid >> 5;
    const int gid = lane >> 2, tig = lane & 3;
    const int wm = warp >> 1, wn = warp & 1;           // 4 x 2 warps, 32x64 tiles
    const int m0 = blockIdx.y * 128, n0 = blockIdx.x * 128;

    float acc[2][8][4];
#pragma unroll
    for (int i = 0; i < 2; i++)
#pragma unroll
        for (int j = 0; j < 8; j++)
#pragma unroll
            for (int l = 0; l < 4; l++) acc[i][j][l] = 0.0f;

    // ---- cp.async: 4 x 16B chunks per thread (A 512 + B 512) ----
    const uint32_t* gsrc[4];
    uint32_t sdst[4];
#pragma unroll
    for (int i = 0; i < 2; i++) {          // A: 128 rows x 4 parts
        int idx = tid + i * 256;
        int r = idx >> 2, part = idx & 3;
        gsrc[i] = g_bf + W_AH + (size_t)(m0 + r) * KPW + part * 4;
        sdst[i] = sb32 + (uint32_t)(r * 80 + part * 16);
    }
#pragma unroll
    for (int i = 0; i < 2; i++) {          // B: 128 rows x 4 parts
        int idx = tid + i * 256;
        int r = idx >> 2, part = idx & 3;
        gsrc[2 + i] = g_bf + W_BH + (size_t)(n0 + r) * KPW + part * 4;
        sdst[2 + i] = sb32 + (uint32_t)(10240 + r * 80 + part * 16);
    }

    auto issue = [&](int t) {
        const uint32_t boff = (uint32_t)(t % 3) * STG;
        const size_t k = (size_t)t * 16;
#pragma unroll
        for (int i = 0; i < 4; i++)
            asm volatile("cp.async.cg.shared.global [%0], [%1], 16;"
                         :: "r"(sdst[i] + boff), "l"(gsrc[i] + k) : "memory");
        asm volatile("cp.async.commit_group;" ::: "memory");
    };

    const int lr = (lane & 7) + ((lane >> 3) & 1) * 8;
    const int kb = ((lane >> 4) & 1) * 16;
    const uint32_t aoff = (uint32_t)((wm * 32 + lr) * 80 + kb);
    const uint32_t boff2 = (uint32_t)(10240 + (wn * 64 + lr) * 80 + kb);

    issue(0);
    issue(1);

    for (int t = 0; t < G1NT; t++) {
        if (t == G1NT - 1) asm volatile("cp.async.wait_group 0;" ::: "memory");
        else               asm volatile("cp.async.wait_group 1;" ::: "memory");
        __syncthreads();
        if (t + 2 < G1NT) issue(t + 2);

        const uint32_t st = sb32 + (uint32_t)(t % 3) * STG;
#pragma unroll
        for (int kkw = 0; kkw < 2; kkw++) {
            const uint32_t ka = st + kkw * 32;
            uint32_t ah[2][4], bq[4][4];
#pragma unroll
            for (int ms = 0; ms < 2; ms++)
                ldsm_x4(ah[ms][0], ah[ms][1], ah[ms][2], ah[ms][3],
                        ka + aoff + ms * 1280);
#pragma unroll
            for (int pr = 0; pr < 4; pr++)
                ldsm_x4(bq[pr][0], bq[pr][1], bq[pr][2], bq[pr][3],
                        ka + boff2 + pr * 1280);
#pragma unroll
            for (int ms = 0; ms < 2; ms++)
#pragma unroll
                for (int pr = 0; pr < 4; pr++)
#pragma unroll
                    for (int j = 0; j < 2; j++) {
                        int ns = pr * 2 + j;
                        mma_f16(acc[ms][ns], ah[ms][0], ah[ms][1], ah[ms][2], ah[ms][3],
                                bq[pr][j], bq[pr][j + 2]);
                    }
        }
    }

    // epilogue
#pragma unroll
    for (int ms = 0; ms < 2; ms++) {
        const int r0 = m0 + wm * 32 + ms * 16 + gid;
#pragma unroll
        for (int ns = 0; ns < 8; ns++) {
            const int c0 = n0 + wn * 64 + ns * 8 + 2 * tig;
            const float bv0 = bias[c0], bv1 = bias[c0 + 1];
            C[(size_t)r0 * E1 + c0]           = softplusf(acc[ms][ns][0] + bv0);
            C[(size_t)r0 * E1 + c0 + 1]       = softplusf(acc[ms][ns][1] + bv1);
            C[(size_t)(r0 + 8) * E1 + c0]     = softplusf(acc[ms][ns][2] + bv0);
            C[(size_t)(r0 + 8) * E1 + c0 + 1] = softplusf(acc[ms][ns][3] + bv1);
        }
    }
}

// ============================ bf16x3 NT GEMM (en2 + logits) ==================
#define NTB_SMEM (2 * 10240 * 4)

template<bool SP, bool HB, bool CHKMN>
__global__ void __launch_bounds__(512, 1)
gemm_nt_bf16x3(const float* __restrict__ A, const float* __restrict__ B,
               const float* __restrict__ bias, float* __restrict__ C,
               int M, int N, int K)
{
    extern __shared__ __align__(16) uint32_t sw[];
    const int tid = threadIdx.x;
    const int lane = tid & 31, warp = tid >> 5;
    const int gid = lane >> 2, tig = lane & 3;
    const int wm = warp >> 2, wn = warp & 3;
    const int m0 = blockIdx.y * 128, n0 = blockIdx.x * 128;
    const int nt = (K + 31) / 32;

    float acc[2][4][4];
#pragma unroll
    for (int i = 0; i < 2; i++)
#pragma unroll
        for (int j = 0; j < 4; j++)
#pragma unroll
            for (int l = 0; l < 4; l++) acc[i][j][l] = 0.0f;

    const int srow = tid >> 3;
    const int sq   = tid & 7;
    float4 stA[2], stB[2];

    auto load_tile = [&](int t) {
        const int gk = t * 32 + sq * 4;
#pragma unroll
        for (int l = 0; l < 2; l++) {
            int r = srow + l * 64;
            {
                int gm = m0 + r;
                float4 v = make_float4(0.f, 0.f, 0.f, 0.f);
                if (((!CHKMN) || gm < M)) {
                    if (gk + 3 < K) v = *reinterpret_cast<const float4*>(A + (size_t)gm * K + gk);
                    else if (gk < K) {
                        const float* p = A + (size_t)gm * K;
                        v.x = p[gk];
                        if (gk + 1 < K) v.y = p[gk + 1];
                        if (gk + 2 < K) v.z = p[gk + 2];
                    }
                }
                stA[l] = v;
            }
            {
                int gn = n0 + r;
                float4 v = make_float4(0.f, 0.f, 0.f, 0.f);
                if (((!CHKMN) || gn < N)) {
                    if (gk + 3 < K) v = *reinterpret_cast<const float4*>(B + (size_t)gn * K + gk);
                    else if (gk < K) {
                        const float* p = B + (size_t)gn * K;
                        v.x = p[gk];
                        if (gk + 1 < K) v.y = p[gk + 1];
                        if (gk + 2 < K) v.z = p[gk + 2];
                    }
                }
                stB[l] = v;
            }
        }
    };

    auto store_tile = [&](uint32_t* buf) {
#pragma unroll
        for (int l = 0; l < 2; l++) {
            int r = srow + l * 64;
            uint32_t w = (uint32_t)(r * 20 + sq * 2);
            {
                float4 v = stA[l];
                __nv_bfloat16 hx = __float2bfloat16_rn(v.x), hy = __float2bfloat16_rn(v.y);
                __nv_bfloat16 hz = __float2bfloat16_rn(v.z), hw = __float2bfloat16_rn(v.w);
                buf[w]     = ((uint32_t)__bfloat16_as_ushort(hy) << 16) | __bfloat16_as_ushort(hx);
                buf[w + 1] = ((uint32_t)__bfloat16_as_ushort(hw) << 16) | __bfloat16_as_ushort(hz);
                buf[w + 2560]     = pk_bf16(v.x - __bfloat162float(hx), v.y - __bfloat162float(hy));
                buf[w + 2560 + 1] = pk_bf16(v.z - __bfloat162float(hz), v.w - __bfloat162float(hw));
            }
            {
                float4 v = stB[l];
                __nv_bfloat16 hx = __float2bfloat16_rn(v.x), hy = __float2bfloat16_rn(v.y);
                __nv_bfloat16 hz = __float2bfloat16_rn(v.z), hw = __float2bfloat16_rn(v.w);
                buf[w + 5120]     = ((uint32_t)__bfloat16_as_ushort(hy) << 16) | __bfloat16_as_ushort(hx);
                buf[w + 5120 + 1] = ((uint32_t)__bfloat16_as_ushort(hw) << 16) | __bfloat16_as_ushort(hz);
                buf[w + 7680]     = pk_bf16(v.x - __bfloat162float(hx), v.y - __bfloat162float(hy));
                buf[w + 7680 + 1] = pk_bf16(v.z - __bfloat162float(hz), v.w - __bfloat162float(hw));
            }
        }
    };

    load_tile(0);
    store_tile(sw);
    __syncthreads();

    for (int t = 0; t < nt; t++) {
        const int b = t & 1;
        uint32_t* bb = sw + b * 10240;
        if (t + 1 < nt) load_tile(t + 1);

#pragma unroll
        for (int kkw = 0; kkw < 16; kkw += 8) {
            uint32_t ah[2][4], al[2][4], bh[4][2], bl[4][2];
#pragma unroll
            for (int ms = 0; ms < 2; ms++) {
                int base = (wm * 32 + ms * 16 + gid) * 20 + kkw + tig;
                ah[ms][0] = bb[base];       ah[ms][1] = bb[base + 160];
                ah[ms][2] = bb[base + 4];   ah[ms][3] = bb[base + 164];
                al[ms][0] = bb[base + 2560];       al[ms][1] = bb[base + 2560 + 160];
                al[ms][2] = bb[base + 2560 + 4];   al[ms][3] = bb[base + 2560 + 164];
            }
#pragma unroll
            for (int ns = 0; ns < 4; ns++) {
                int base = 5120 + (wn * 32 + ns * 8 + gid) * 20 + kkw + tig;
                bh[ns][0] = bb[base];       bh[ns][1] = bb[base + 4];
                bl[ns][0] = bb[base + 2560]; bl[ns][1] = bb[base + 2560 + 4];
            }
#pragma unroll
            for (int ms = 0; ms < 2; ms++)
#pragma unroll
                for (int ns = 0; ns < 4; ns++) {
                    mma_bf16(acc[ms][ns], ah[ms][0], ah[ms][1], ah[ms][2], ah[ms][3],
                             bh[ns][0], bh[ns][1]);
                    mma_bf16(acc[ms][ns], ah[ms][0], ah[ms][1], ah[ms][2], ah[ms][3],
                             bl[ns][0], bl[ns][1]);
                    mma_bf16(acc[ms][ns], al[ms][0], al[ms][1], al[ms][2], al[ms][3],
                             bh[ns][0], bh[ns][1]);
                }
        }

        if (t + 1 < nt) store_tile(sw + (b ^ 1) * 10240);
        __syncthreads();
    }

#pragma unroll
    for (int ms = 0; ms < 2; ms++) {
        int r0 = m0 + wm * 32 + ms * 16 + gid;
#pragma unroll
        for (int ns = 0; ns < 4; ns++) {
            int c0 = n0 + wn * 32 + ns * 8 + 2 * tig;
            float bv0 = 0.f, bv1 = 0.f;
            if (HB) { bv0 = bias[c0]; bv1 = bias[c0 + 1]; }
            float v00 = acc[ms][ns][0] + bv0;
            float v01 = acc[ms][ns][1] + bv1;
            float v10 = acc[ms][ns][2] + bv0;
            float v11 = acc[ms][ns][3] + bv1;
            if (SP) { v00 = softplusf(v00); v01 = softplusf(v01);
                      v10 = softplusf(v10); v11 = softplusf(v11); }
            if (!CHKMN) {
                C[(size_t)r0 * N + c0]           = v00;
                C[(size_t)r0 * N + c0 + 1]       = v01;
                C[(size_t)(r0 + 8) * N + c0]     = v10;
                C[(size_t)(r0 + 8) * N + c0 + 1] = v11;
            } else {
                if (r0 < M) {
                    if (c0 < N)     C[(size_t)r0 * N + c0]     = v00;
                    if (c0 + 1 < N) C[(size_t)r0 * N + c0 + 1] = v01;
                }
                if (r0 + 8 < M) {
                    if (c0 < N)     C[(size_t)(r0 + 8) * N + c0]     = v10;
                    if (c0 + 1 < N) C[(size_t)(r0 + 8) * N + c0 + 1] = v11;
                }
            }
        }
    }
}

// ============================ tf32 recon =====================================
__device__ __forceinline__ unsigned tf32_rna(float x) {
    unsigned r;
    asm("cvt.rna.tf32.f32 %0, %1;" : "=r"(r) : "f"(x));
    return r;
}

__device__ __forceinline__ void mma_tf32(float* d,
                                         unsigned a0, unsigned a1, unsigned a2, unsigned a3,
                                         unsigned b0, unsigned b1)
{
    asm volatile(
        "mma.sync.aligned.m16n8k8.row.col.f32.tf32.tf32.f32 "
        "{%0,%1,%2,%3},{%4,%5,%6,%7},{%8,%9},{%0,%1,%2,%3};"
        : "+f"(d[0]), "+f"(d[1]), "+f"(d[2]), "+f"(d[3])
        : "r"(a0), "r"(a1), "r"(a2), "r"(a3), "r"(b0), "r"(b1));
}

__global__ void __launch_bounds__(256, 2)
recon_tf32(const float* __restrict__ A, const float* __restrict__ B,
           float* __restrict__ C)
{
    __shared__ float Ah[128][20];
    __shared__ float Bh[16][136];
    const int tid = threadIdx.x;
    const int lane = tid & 31, warp = tid >> 5;
    const int gid = lane >> 2, tig = lane & 3;
    const int wm = warp >> 1, wn = warp & 1;
    const int m0 = blockIdx.y * 128;
    const int n0 = blockIdx.x * 128;

    float acc[2][8][4];
#pragma unroll
    for (int i = 0; i < 2; i++)
#pragma unroll
        for (int j = 0; j < 8; j++)
#pragma unroll
            for (int l = 0; l < 4; l++) acc[i][j][l] = 0.0f;

    for (int k0 = 0; k0 < KK; k0 += 16) {
#pragma unroll
        for (int l = 0; l < 2; l++) {
            int idx = tid + l * 256;
            int row = idx >> 2, kq = (idx & 3) * 4;
            int gk = k0 + kq;
            float4 v = make_float4(0.f, 0.f, 0.f, 0.f);
            if (gk + 3 < KK)
                v = *reinterpret_cast<const float4*>(A + (size_t)(m0 + row) * KK + gk);
            Ah[row][kq + 0] = __uint_as_float(tf32_rna(v.x));
            Ah[row][kq + 1] = __uint_as_float(tf32_rna(v.y));
            Ah[row][kq + 2] = __uint_as_float(tf32_rna(v.z));
            Ah[row][kq + 3] = __uint_as_float(tf32_rna(v.w));
        }
#pragma unroll
        for (int l = 0; l < 2; l++) {
            int idx = tid + l * 256;
            int kk = idx >> 5, nc = (idx & 31) * 4;
            int gk = k0 + kk, gn = n0 + nc;
            float4 v = make_float4(0.f, 0.f, 0.f, 0.f);
            if (gk < KK && gn + 3 < VV)
                v = *reinterpret_cast<const float4*>(B + (size_t)gk * VV + gn);
            Bh[kk][nc + 0] = __uint_as_float(tf32_rna(v.x));
            Bh[kk][nc + 1] = __uint_as_float(tf32_rna(v.y));
            Bh[kk][nc + 2] = __uint_as_float(tf32_rna(v.z));
            Bh[kk][nc + 3] = __uint_as_float(tf32_rna(v.w));
        }
        __syncthreads();

#pragma unroll
        for (int kk = 0; kk < 16; kk += 8) {
            unsigned a[2][4], b[8][2];
#pragma unroll
            for (int ms = 0; ms < 2; ms++) {
                int r = wm * 32 + ms * 16 + gid;
                a[ms][0] = __float_as_uint(Ah[r][kk + tig]);
                a[ms][1] = __float_as_uint(Ah[r + 8][kk + tig]);
                a[ms][2] = __float_as_uint(Ah[r][kk + tig + 4]);
                a[ms][3] = __float_as_uint(Ah[r + 8][kk + tig + 4]);
            }
#pragma unroll
            for (int ns = 0; ns < 8; ns++) {
                int n = wn * 64 + ns * 8 + gid;
                b[ns][0] = __float_as_uint(Bh[kk + tig][n]);
                b[ns][1] = __float_as_uint(Bh[kk + tig + 4][n]);
            }
#pragma unroll
            for (int ms = 0; ms < 2; ms++)
#pragma unroll
                for (int ns = 0; ns < 8; ns++)
                    mma_tf32(acc[ms][ns], a[ms][0], a[ms][1], a[ms][2], a[ms][3],
                             b[ns][0], b[ns][1]);
        }
        __syncthreads();
    }

#pragma unroll
    for (int ms = 0; ms < 2; ms++) {
        int r0 = m0 + wm * 32 + ms * 16 + gid;
#pragma unroll
        for (int ns = 0; ns < 8; ns++) {
            int c0 = n0 + wn * 64 + ns * 8 + 2 * tig;
            if (c0 < VV) {
                C[(size_t)r0 * VV + c0]       = acc[ms][ns][0];
                C[(size_t)(r0 + 8) * VV + c0] = acc[ms][ns][2];
            }
            if (c0 + 1 < VV) {
                C[(size_t)r0 * VV + c0 + 1]       = acc[ms][ns][1];
                C[(size_t)(r0 + 8) * VV + c0 + 1] = acc[ms][ns][3];
            }
        }
    }
}

// ---------------- mean / logvar heads ---------------------------------------
__global__ void meanlogvar_kernel(const float* __restrict__ en2,
                                  const float* __restrict__ mW, const float* __restrict__ mb,
                                  const float* __restrict__ lW, const float* __restrict__ lb,
                                  float* __restrict__ pm, float* __restrict__ lv)
{
    int t = blockIdx.x * blockDim.x + threadIdx.x;
    if (t >= NB * 4) return;
    int n = t >> 2, j = t & 3;
    const float* w = (j < 2) ? (mW + j * E2) : (lW + (j - 2) * E2);
    const float* x = en2 + (size_t)n * E2;
    float s = 0.f;
    for (int i = 0; i < E2; i += 4) {
        float4 xa = *reinterpret_cast<const float4*>(x + i);
        float4 wa = *reinterpret_cast<const float4*>(w + i);
        s += xa.x * wa.x + xa.y * wa.y + xa.z * wa.z + xa.w * wa.w;
    }
    if (j < 2) pm[n * 2 + j] = s + mb[j];
    else       lv[n * 2 + (j - 2)] = s + lb[j - 2];
}

// ---------------- column stats of (R x 2) -----------------------------------
__global__ void colstats_kernel(const float* __restrict__ X, int R, float* __restrict__ out)
{
    __shared__ float ss[256], s2[256];
    int c = blockIdx.x, tid = threadIdx.x;
    float s = 0.f, q = 0.f;
    for (int r = tid; r < R; r += 256) {
        float x = X[r * 2 + c];
        s += x; q += x * x;
    }
    ss[tid] = s; s2[tid] = q;
    __syncthreads();
    for (int st = 128; st > 0; st >>= 1) {
        if (tid < st) { ss[tid] += ss[tid + st]; s2[tid] += s2[tid + st]; }
        __syncthreads();
    }
    if (tid == 0) {
        float m = ss[0] / R;
        out[c] = m;
        out[2 + c] = s2[0] / R - m * m;
    }
}

// ---------------- z ----------------------------------------------------------
__global__ void z_kernel(const float* __restrict__ pm, const float* __restrict__ lv,
                         const float* __restrict__ spm, const float* __restrict__ slv,
                         const float* __restrict__ gm, const float* __restrict__ bm,
                         const float* __restrict__ gl, const float* __restrict__ bl,
                         const float* __restrict__ eps,
                         float* __restrict__ gz, float* __restrict__ outz)
{
    int idx = blockIdx.x * 256 + threadIdx.x;
    if (idx >= NB * CC) return;
    int c = idx & 1;
    float pmb = gm[c] * (pm[idx] - spm[c]) * rsqrtf(spm[2 + c] + 1e-5f) + bm[c];
    float lvb = gl[c] * (lv[idx] - slv[c]) * rsqrtf(slv[2 + c] + 1e-5f) + bl[c];
    float z = pmb + sqrtf(expf(lvb)) * eps[idx];
    gz[idx] = z;
    outz[idx] = z;
}

// ---------------- BN apply ---------------------------------------------------
__global__ void bn_apply_kernel(const float* __restrict__ X, const float* __restrict__ stats,
                                const float* __restrict__ g, const float* __restrict__ b,
                                int total, float* __restrict__ o1, float* __restrict__ o2)
{
    int idx = blockIdx.x * 256 + threadIdx.x;
    if (idx >= total) return;
    int c = idx & 1;
    float y = g[c] * (X[idx] - stats[c]) * rsqrtf(stats[2 + c] + 1e-5f) + b[c];
    o1[idx] = y;
    o2[idx] = y;
}

// ---------------- theta ------------------------------------------------------
__global__ void theta_kernel(const float* __restrict__ zx, const float* __restrict__ zc,
                             float* __restrict__ gtheta, float* __restrict__ otheta)
{
    __shared__ float sz[KK * 2];
    __shared__ float red[256];
    int n = blockIdx.x, tid = threadIdx.x;
    for (int i = tid; i < KK * 2; i += 256) sz[i] = zc[i];
    __syncthreads();
    float x0 = zx[n * 2], x1 = zx[n * 2 + 1];
    float l = -FLT_MAX;
    if (tid < KK) {
        float dx = x0 - sz[tid * 2];
        float dy = x1 - sz[tid * 2 + 1];
        l = -0.5f * (dx * dx + dy * dy);
    }
    red[tid] = l;
    __syncthreads();
    for (int st = 128; st > 0; st >>= 1) {
        if (tid < st) red[tid] = fmaxf(red[tid], red[tid + st]);
        __syncthreads();
    }
    float mx = red[0];
    __syncthreads();
    float e = (tid < KK) ? expf(l - mx) : 0.f;
    red[tid] = e;
    __syncthreads();
    for (int st = 128; st > 0; st >>= 1) {
        if (tid < st) red[tid] += red[tid + st];
        __syncthreads();
    }
    float inv = 1.f / red[0];
    if (tid < KK) {
        float th = e * inv;
        gtheta[(size_t)n * KK + tid] = th;
        otheta[(size_t)n * KK + tid] = th;
    }
}

// ---------------- decoder MLP ------------------------------------------------
__global__ void mu1_kernel(const float* __restrict__ zc, const float* __restrict__ W,
                           const float* __restrict__ b, float* __restrict__ out)
{
    int t = blockIdx.x * 256 + threadIdx.x;
    if (t >= KK * 100) return;
    int k = t / 100, j = t % 100;
    float v = zc[k * 2] * W[j * 2] + zc[k * 2 + 1] * W[j * 2 + 1] + b[j];
    out[t] = softplusf(v);
}

__global__ void mu2_kernel(const float* __restrict__ mu1, const float* __restrict__ W,
                           const float* __restrict__ b, float* __restrict__ out)
{
    __shared__ float row[100];
    int k = blockIdx.x, tid = threadIdx.x;
    if (tid < 100) row[tid] = mu1[k * 100 + tid];
    __syncthreads();
    if (tid < 100) {
        const float* w = W + tid * 100;
        float s = b[tid];
        for (int i = 0; i < 100; i++) s += row[i] * w[i];
        out[k * 100 + tid] = softplusf(s);
    }
}

__global__ void muz_kernel(const float* __restrict__ mu2, const float* __restrict__ W,
                           const float* __restrict__ b, float* __restrict__ out)
{
    __shared__ float row[100];
    int k = blockIdx.x, tid = threadIdx.x;
    if (tid < 100) row[tid] = mu2[k * 100 + tid];
    __syncthreads();
    for (int j = tid; j < EMB; j += 128) {
        const float* w = W + j * 100;
        float s = b[j];
        for (int i = 0; i < 100; i++) s += row[i] * w[i];
        out[k * EMB + j] = s;
    }
}

// ---------------- beta -------------------------------------------------------
__global__ void __launch_bounds__(1024)
beta_kernel(const float* __restrict__ logits, const float* __restrict__ bbias,
            const float* __restrict__ gdec, const float* __restrict__ bdec,
            float* __restrict__ beta)
{
    __shared__ float red[1024];
    __shared__ float red2[1024];
    const int k = blockIdx.x, tid = threadIdx.x;
    const float* row = logits + (size_t)k * VV;
    const float* bb  = bbias + (size_t)k * VV;

    float s = 0.f, q = 0.f;
    for (int v = tid; v < VV; v += 1024) { float x = row[v]; s += x; q += x * x; }
    red[tid] = s; red2[tid] = q;
    __syncthreads();
    for (int st = 512; st > 0; st >>= 1) {
        if (tid < st) { red[tid] += red[tid + st]; red2[tid] += red2[tid + st]; }
        __syncthreads();
    }
    float mean = red[0] / VV;
    float var  = red2[0] / VV - mean * mean;
    float scale = gdec[k] * rsqrtf(var + 1e-5f);
    float shift = bdec[k] - mean * scale;
    __syncthreads();

    float mx = -FLT_MAX;
    for (int v = tid; v < VV; v += 1024) {
        float y = row[v] * scale + shift + bb[v];
        mx = fmaxf(mx, y);
    }
    red[tid] = mx;
    __syncthreads();
    for (int st = 512; st > 0; st >>= 1) {
        if (tid < st) red[tid] = fmaxf(red[tid], red[tid + st]);
        __syncthreads();
    }
    mx = red[0];
    __syncthreads();

    float se = 0.f;
    for (int v = tid; v < VV; v += 1024) {
        float y = row[v] * scale + shift + bb[v];
        se += expf(y - mx);
    }
    red[tid] = se;
    __syncthreads();
    for (int st = 512; st > 0; st >>= 1) {
        if (tid < st) red[tid] += red[tid + st];
        __syncthreads();
    }
    float inv = 1.f / red[0];

    for (int v = tid; v < VV; v += 1024) {
        float y = row[v] * scale + shift + bb[v];
        beta[(size_t)k * VV + v] = expf(y - mx) * inv;
    }
}

// ---------------- launch -----------------------------------------------------
extern "C" void kernel_launch(void* const* d_in, const int* in_sizes, int n_in,
                              void* d_out, int out_size)
{
    const float* input_   = (const float*)d_in[0];
    const float* eps      = (const float*)d_in[2];
    const float* en1_W    = (const float*)d_in[3];
    const float* en1_b    = (const float*)d_in[4];
    const float* en2_W    = (const float*)d_in[5];
    const float* en2_b    = (const float*)d_in[6];
    const float* mean_W   = (const float*)d_in[7];
    const float* mean_b   = (const float*)d_in[8];
    const float* logvar_W = (const float*)d_in[9];
    const float* logvar_b = (const float*)d_in[10];
    const float* mu1_W    = (const float*)d_in[11];
    const float* mu1_b    = (const float*)d_in[12];
    const float* mu2_W    = (const float*)d_in[13];
    const float* mu2_b    = (const float*)d_in[14];
    const float* mu_W     = (const float*)d_in[15];
    const float* mu_b     = (const float*)d_in[16];
    const float* topics   = (const float*)d_in[17];
    const float* bbias    = (const float*)d_in[18];
    const float* emb      = (const float*)d_in[19];
    const float* g_mean   = (const float*)d_in[20];
    const float* b_mean   = (const float*)d_in[21];
    const float* g_logvar = (const float*)d_in[22];
    const float* b_logvar = (const float*)d_in[23];
    const float* g_x      = (const float*)d_in[24];
    const float* b_x      = (const float*)d_in[25];
    const float* g_phi    = (const float*)d_in[26];
    const float* b_phi    = (const float*)d_in[27];
    const float* g_dec    = (const float*)d_in[28];
    const float* b_dec    = (const float*)d_in[29];

    float* out = (float*)d_out;
    float* out_z     = out;
    float* out_recon = out + (long long)NB * CC;
    float* out_zx    = out_recon + (long long)NB * VV;
    float* out_zc    = out_zx + (long long)NB * CC;
    float* out_theta = out_zc + (long long)KK * CC;

    void* sp = nullptr;
    cudaGetSymbolAddress(&sp, g_scratch);
    float* S = (float*)sp;
    float* s_en1    = S + OFF_EN1;
    float* s_en2    = S + OFF_EN2;
    float* s_pm     = S + OFF_PM;
    float* s_lv     = S + OFF_LV;
    float* s_z      = S + OFF_Z;
    float* s_zx     = S + OFF_ZX;
    float* s_zc     = S + OFF_ZC;
    float* s_theta  = S + OFF_THETA;
    float* s_mu1    = S + OFF_MU1;
    float* s_mu2    = S + OFF_MU2;
    float* s_muz    = S + OFF_MUZ;
    float* s_logits = S + OFF_LOGITS;
    float* s_beta   = S + OFF_BETA;
    float* st_pm    = S + OFF_SPM;
    float* st_lv    = S + OFF_SLV;
    float* st_z     = S + OFF_SZ;
    float* st_t     = S + OFF_ST;

    cudaFuncSetAttribute(gemm1_fp16, cudaFuncAttributeMaxDynamicSharedMemorySize, G1_SMEM);
    cudaFuncSetAttribute(gemm_nt_bf16x3<true, true, false>,
                         cudaFuncAttributeMaxDynamicSharedMemorySize, NTB_SMEM);
    cudaFuncSetAttribute(gemm_nt_bf16x3<false, false, true>,
                         cudaFuncAttributeMaxDynamicSharedMemorySize, NTB_SMEM);

    // 0) pre-split: A -> 1 fp16 plane, B -> 1 fp16 plane
    split_fp16<<<NB + E1, 256>>>(input_, en1_W);

    // 1-4) decoder-side small kernels
    colstats_kernel<<<2, 256>>>(topics, KK, st_t);
    bn_apply_kernel<<<(KK * CC + 255) / 256, 256>>>(topics, st_t, g_phi, b_phi, KK * CC, s_zc, out_zc);
    mu1_kernel<<<(KK * 100 + 255) / 256, 256>>>(s_zc, mu1_W, mu1_b, s_mu1);
    mu2_kernel<<<KK, 128>>>(s_mu1, mu2_W, mu2_b, s_mu2);

    // 5) en1 = softplus(input @ en1_W^T + b) — plain fp16
    gemm1_fp16<<<dim3(E1 / 128, NB / 128), 256, G1_SMEM>>>(en1_b, s_en1);

    // 6) muz
    muz_kernel<<<KK, 128>>>(s_mu2, mu_W, mu_b, s_muz);

    // 7) en2 — bf16x3
    gemm_nt_bf16x3<true, true, false><<<dim3(E2 / 128, NB / 128), 512, NTB_SMEM>>>(
        s_en1, en2_W, en2_b, s_en2, NB, E2, E1);

    // 8) heads
    meanlogvar_kernel<<<(NB * 4 + 255) / 256, 256>>>(
        s_en2, mean_W, mean_b, logvar_W, logvar_b, s_pm, s_lv);

    // 9-11) BN stats + z
    colstats_kernel<<<2, 256>>>(s_pm, NB, st_pm);
    colstats_kernel<<<2, 256>>>(s_lv, NB, st_lv);
    z_kernel<<<(NB * CC + 255) / 256, 256>>>(
        s_pm, s_lv, st_pm, st_lv, g_mean, b_mean, g_logvar, b_logvar, eps, s_z, out_z);

    // 12-13) zx
    colstats_kernel<<<2, 256>>>(s_z, NB, st_z);
    bn_apply_kernel<<<(NB * CC + 255) / 256, 256>>>(s_z, st_z, g_x, b_x, NB * CC, s_zx, out_zx);

    // 14) theta
    theta_kernel<<<NB, 256>>>(s_zx, s_zc, s_theta, out_theta);

    // 15) logits = mu_z @ emb^T — bf16x3
    gemm_nt_bf16x3<false, false, true><<<dim3((VV + 127) / 128, (KK + 127) / 128), 512, NTB_SMEM>>>(
        s_muz, emb, nullptr, s_logits, KK, VV, EMB);

    // 16) beta
    beta_kernel<<<KK, 1024>>>(s_logits, bbias, g_dec, b_dec, s_beta);

    // 17) recon = theta @ beta — tf32 (precision hedge)
    recon_tf32<<<dim3((VV + 127) / 128, NB / 128), 256>>>(s_theta, s_beta, out_recon);

    (void)in_sizes; (void)n_in; (void)out_size;
}

// round 10
// speedup vs baseline: 1.9874x; 1.0972x over previous
#include <cuda_runtime.h>
#include <cuda_bf16.h>
#include <cuda_fp16.h>
#include <math.h>
#include <float.h>
#include <stdint.h>

// ---------------- problem dims ----------------
#define NB   2048
#define VV   50000
#define E1   1024
#define E2   512
#define CC   2
#define KK   200
#define EMB  300

#define KP   50048              // VV padded to multiple of 32
#define KPW  (KP/2)             // 25024 words per row
#define G1NT (KP / 32)          // 1564 k-tiles

// recon dims: K = KK padded to 224, beta^T rows padded to 50048
#define KR   224
#define KRW  (KR/2)             // 112 words per row
#define RNT  (KR / 32)          // 7 k-tiles
#define BTROWS 50048

// ---------------- float scratch ----------------------------------------------
#define OFF_EN1    0LL
#define OFF_EN2    (OFF_EN1 + (long long)NB*E1)
#define OFF_PM     (OFF_EN2 + (long long)NB*E2)
#define OFF_LV     (OFF_PM + (long long)NB*CC)
#define OFF_Z      (OFF_LV + (long long)NB*CC)
#define OFF_ZX     (OFF_Z + (long long)NB*CC)
#define OFF_ZC     (OFF_ZX + (long long)NB*CC)
#define OFF_THETA  (OFF_ZC + (long long)KK*CC)
#define OFF_MU1    (OFF_THETA + (long long)NB*KK)
#define OFF_MU2    (OFF_MU1 + (long long)KK*100)
#define OFF_MUZ    (OFF_MU2 + (long long)KK*100)
#define OFF_LOGITS (OFF_MUZ + (long long)KK*EMB)
#define OFF_BETA   (OFF_LOGITS + (long long)KK*VV)
#define OFF_SPM    (OFF_BETA + (long long)KK*VV)
#define OFF_SLV    (OFF_SPM + 4)
#define OFF_SZ     (OFF_SLV + 4)
#define OFF_ST     (OFF_SZ + 4)
#define SCRATCH_FLOATS (OFF_ST + 8)

__device__ float g_scratch[SCRATCH_FLOATS];

// ---------------- fp16 planes (words) ----------------------------------------
#define WA 51249152LL                    // NB * KPW
#define WB 25624576LL                    // E1 * KPW
#define W_AH 0LL
#define W_BH (W_AH + WA)
#define W_TH (W_BH + WB)                 // theta fp16: NB x KRW
#define TWH  ((long long)NB * KRW)
#define W_BT (W_TH + TWH)                // beta^T fp16: BTROWS x KRW
#define BTWH ((long long)BTROWS * KRW)

__device__ __align__(16) uint32_t g_bf[WA + WB + TWH + BTWH];

__device__ __forceinline__ float softplusf(float x) {
    return fmaxf(x, 0.0f) + log1pf(expf(-fabsf(x)));
}

__device__ __forceinline__ uint32_t pk_h2(__half lo, __half hi) {
    return ((uint32_t)__half_as_ushort(hi) << 16) | __half_as_ushort(lo);
}

__device__ __forceinline__ uint32_t pk_bf16(float lo, float hi) {
    uint32_t r;
    asm("cvt.rn.bf16x2.f32 %0, %1, %2;" : "=r"(r) : "f"(hi), "f"(lo));
    return r;
}

__device__ __forceinline__ void mma_f16(float* d,
                                        uint32_t a0, uint32_t a1, uint32_t a2, uint32_t a3,
                                        uint32_t b0, uint32_t b1)
{
    asm volatile(
        "mma.sync.aligned.m16n8k16.row.col.f32.f16.f16.f32 "
        "{%0,%1,%2,%3},{%4,%5,%6,%7},{%8,%9},{%0,%1,%2,%3};"
        : "+f"(d[0]), "+f"(d[1]), "+f"(d[2]), "+f"(d[3])
        : "r"(a0), "r"(a1), "r"(a2), "r"(a3), "r"(b0), "r"(b1));
}

__device__ __forceinline__ void mma_bf16(float* d,
                                         uint32_t a0, uint32_t a1, uint32_t a2, uint32_t a3,
                                         uint32_t b0, uint32_t b1)
{
    asm volatile(
        "mma.sync.aligned.m16n8k16.row.col.f32.bf16.bf16.f32 "
        "{%0,%1,%2,%3},{%4,%5,%6,%7},{%8,%9},{%0,%1,%2,%3};"
        : "+f"(d[0]), "+f"(d[1]), "+f"(d[2]), "+f"(d[3])
        : "r"(a0), "r"(a1), "r"(a2), "r"(a3), "r"(b0), "r"(b1));
}

__device__ __forceinline__ void ldsm_x4(uint32_t& r0, uint32_t& r1, uint32_t& r2,
                                        uint32_t& r3, uint32_t addr)
{
    asm volatile("ldmatrix.sync.aligned.m8n8.x4.shared.b16 {%0,%1,%2,%3}, [%4];"
                 : "=r"(r0), "=r"(r1), "=r"(r2), "=r"(r3) : "r"(addr));
}

// =============================================================================
// Pre-pass: A=input -> one fp16 plane; B=en1_W -> one fp16 plane. Zero pad.
// =============================================================================
__global__ void __launch_bounds__(256)
split_fp16(const float* __restrict__ A, const float* __restrict__ B)
{
    const int b = blockIdx.x, tid = threadIdx.x;
    const float* src;
    uint32_t* h;
    if (b < NB) {
        src = A + (size_t)b * VV;
        h = g_bf + W_AH + (size_t)b * KPW;
    } else {
        int r = b - NB;
        src = B + (size_t)r * VV;
        h = g_bf + W_BH + (size_t)r * KPW;
    }
    for (int i = tid; i < VV / 4; i += 256) {
        float4 v = *reinterpret_cast<const float4*>(src + i * 4);
        h[2*i]     = pk_h2(__float2half_rn(v.x), __float2half_rn(v.y));
        h[2*i + 1] = pk_h2(__float2half_rn(v.z), __float2half_rn(v.w));
    }
    if (tid < KPW - VV/2) h[VV/2 + tid] = 0u;
}

// =============================================================================
// GEMM1: en1 = softplus(input @ en1_W^T + b), plain fp16 from pre-split planes.
// Block 128x128, BK=32, 256 threads, 3-stage cp.async + ldmatrix.
// =============================================================================
#define STG    20480
#define G1_SMEM (3 * STG)

__global__ void __launch_bounds__(256, 2)
gemm1_fp16(const float* __restrict__ bias, float* __restrict__ C)
{
    extern __shared__ __align__(16) char sm[];
    const uint32_t sb32 = (uint32_t)__cvta_generic_to_shared(sm);
    const int tid = threadIdx.x;
    const int lane = tid & 31, warp = tid >> 5;
    const int gid = lane >> 2, tig = lane & 3;
    const int wm = warp >> 1, wn = warp & 1;
    const int m0 = blockIdx.y * 128, n0 = blockIdx.x * 128;

    float acc[2][8][4];
#pragma unroll
    for (int i = 0; i < 2; i++)
#pragma unroll
        for (int j = 0; j < 8; j++)
#pragma unroll
            for (int l = 0; l < 4; l++) acc[i][j][l] = 0.0f;

    const uint32_t* gsrc[4];
    uint32_t sdst[4];
#pragma unroll
    for (int i = 0; i < 2; i++) {
        int idx = tid + i * 256;
        int r = idx >> 2, part = idx & 3;
        gsrc[i] = g_bf + W_AH + (size_t)(m0 + r) * KPW + part * 4;
        sdst[i] = sb32 + (uint32_t)(r * 80 + part * 16);
    }
#pragma unroll
    for (int i = 0; i < 2; i++) {
        int idx = tid + i * 256;
        int r = idx >> 2, part = idx & 3;
        gsrc[2 + i] = g_bf + W_BH + (size_t)(n0 + r) * KPW + part * 4;
        sdst[2 + i] = sb32 + (uint32_t)(10240 + r * 80 + part * 16);
    }

    auto issue = [&](int t) {
        const uint32_t boff = (uint32_t)(t % 3) * STG;
        const size_t k = (size_t)t * 16;
#pragma unroll
        for (int i = 0; i < 4; i++)
            asm volatile("cp.async.cg.shared.global [%0], [%1], 16;"
                         :: "r"(sdst[i] + boff), "l"(gsrc[i] + k) : "memory");
        asm volatile("cp.async.commit_group;" ::: "memory");
    };

    const int lr = (lane & 7) + ((lane >> 3) & 1) * 8;
    const int kb = ((lane >> 4) & 1) * 16;
    const uint32_t aoff = (uint32_t)((wm * 32 + lr) * 80 + kb);
    const uint32_t boff2 = (uint32_t)(10240 + (wn * 64 + lr) * 80 + kb);

    issue(0);
    issue(1);

    for (int t = 0; t < G1NT; t++) {
        if (t == G1NT - 1) asm volatile("cp.async.wait_group 0;" ::: "memory");
        else               asm volatile("cp.async.wait_group 1;" ::: "memory");
        __syncthreads();
        if (t + 2 < G1NT) issue(t + 2);

        const uint32_t st = sb32 + (uint32_t)(t % 3) * STG;
#pragma unroll
        for (int kkw = 0; kkw < 2; kkw++) {
            const uint32_t ka = st + kkw * 32;
            uint32_t ah[2][4], bq[4][4];
#pragma unroll
            for (int ms = 0; ms < 2; ms++)
                ldsm_x4(ah[ms][0], ah[ms][1], ah[ms][2], ah[ms][3],
                        ka + aoff + ms * 1280);
#pragma unroll
            for (int pr = 0; pr < 4; pr++)
                ldsm_x4(bq[pr][0], bq[pr][1], bq[pr][2], bq[pr][3],
                        ka + boff2 + pr * 1280);
#pragma unroll
            for (int ms = 0; ms < 2; ms++)
#pragma unroll
                for (int pr = 0; pr < 4; pr++)
#pragma unroll
                    for (int j = 0; j < 2; j++) {
                        int ns = pr * 2 + j;
                        mma_f16(acc[ms][ns], ah[ms][0], ah[ms][1], ah[ms][2], ah[ms][3],
                                bq[pr][j], bq[pr][j + 2]);
                    }
        }
    }

#pragma unroll
    for (int ms = 0; ms < 2; ms++) {
        const int r0 = m0 + wm * 32 + ms * 16 + gid;
#pragma unroll
        for (int ns = 0; ns < 8; ns++) {
            const int c0 = n0 + wn * 64 + ns * 8 + 2 * tig;
            const float bv0 = bias[c0], bv1 = bias[c0 + 1];
            C[(size_t)r0 * E1 + c0]           = softplusf(acc[ms][ns][0] + bv0);
            C[(size_t)r0 * E1 + c0 + 1]       = softplusf(acc[ms][ns][1] + bv1);
            C[(size_t)(r0 + 8) * E1 + c0]     = softplusf(acc[ms][ns][2] + bv0);
            C[(size_t)(r0 + 8) * E1 + c0 + 1] = softplusf(acc[ms][ns][3] + bv1);
        }
    }
}

// =============================================================================
// recon = theta @ beta via NT fp16: A = theta fp16 [2048 x 224], B = beta^T
// fp16 [50048 x 224]. Same structure as gemm1_fp16, 2-deep pipeline, 7 tiles.
// =============================================================================
__global__ void __launch_bounds__(256, 2)
recon_f16(float* __restrict__ C)
{
    extern __shared__ __align__(16) char sm[];
    const uint32_t sb32 = (uint32_t)__cvta_generic_to_shared(sm);
    const int tid = threadIdx.x;
    const int lane = tid & 31, warp = tid >> 5;
    const int gid = lane >> 2, tig = lane & 3;
    const int wm = warp >> 1, wn = warp & 1;
    const int m0 = blockIdx.y * 128, n0 = blockIdx.x * 128;

    float acc[2][8][4];
#pragma unroll
    for (int i = 0; i < 2; i++)
#pragma unroll
        for (int j = 0; j < 8; j++)
#pragma unroll
            for (int l = 0; l < 4; l++) acc[i][j][l] = 0.0f;

    const uint32_t* gsrc[4];
    uint32_t sdst[4];
#pragma unroll
    for (int i = 0; i < 2; i++) {
        int idx = tid + i * 256;
        int r = idx >> 2, part = idx & 3;
        gsrc[i] = g_bf + W_TH + (size_t)(m0 + r) * KRW + part * 4;
        sdst[i] = sb32 + (uint32_t)(r * 80 + part * 16);
    }
#pragma unroll
    for (int i = 0; i < 2; i++) {
        int idx = tid + i * 256;
        int r = idx >> 2, part = idx & 3;
        gsrc[2 + i] = g_bf + W_BT + (size_t)(n0 + r) * KRW + part * 4;
        sdst[2 + i] = sb32 + (uint32_t)(10240 + r * 80 + part * 16);
    }

    auto issue = [&](int t) {
        const uint32_t boff = (uint32_t)(t % 3) * STG;
        const size_t k = (size_t)t * 16;
#pragma unroll
        for (int i = 0; i < 4; i++)
            asm volatile("cp.async.cg.shared.global [%0], [%1], 16;"
                         :: "r"(sdst[i] + boff), "l"(gsrc[i] + k) : "memory");
        asm volatile("cp.async.commit_group;" ::: "memory");
    };

    const int lr = (lane & 7) + ((lane >> 3) & 1) * 8;
    const int kb = ((lane >> 4) & 1) * 16;
    const uint32_t aoff = (uint32_t)((wm * 32 + lr) * 80 + kb);
    const uint32_t boff2 = (uint32_t)(10240 + (wn * 64 + lr) * 80 + kb);

    issue(0);
    issue(1);

    for (int t = 0; t < RNT; t++) {
        if (t == RNT - 1) asm volatile("cp.async.wait_group 0;" ::: "memory");
        else              asm volatile("cp.async.wait_group 1;" ::: "memory");
        __syncthreads();
        if (t + 2 < RNT) issue(t + 2);

        const uint32_t st = sb32 + (uint32_t)(t % 3) * STG;
#pragma unroll
        for (int kkw = 0; kkw < 2; kkw++) {
            const uint32_t ka = st + kkw * 32;
            uint32_t ah[2][4], bq[4][4];
#pragma unroll
            for (int ms = 0; ms < 2; ms++)
                ldsm_x4(ah[ms][0], ah[ms][1], ah[ms][2], ah[ms][3],
                        ka + aoff + ms * 1280);
#pragma unroll
            for (int pr = 0; pr < 4; pr++)
                ldsm_x4(bq[pr][0], bq[pr][1], bq[pr][2], bq[pr][3],
                        ka + boff2 + pr * 1280);
#pragma unroll
            for (int ms = 0; ms < 2; ms++)
#pragma unroll
                for (int pr = 0; pr < 4; pr++)
#pragma unroll
                    for (int j = 0; j < 2; j++) {
                        int ns = pr * 2 + j;
                        mma_f16(acc[ms][ns], ah[ms][0], ah[ms][1], ah[ms][2], ah[ms][3],
                                bq[pr][j], bq[pr][j + 2]);
                    }
        }
    }

#pragma unroll
    for (int ms = 0; ms < 2; ms++) {
        const int r0 = m0 + wm * 32 + ms * 16 + gid;
#pragma unroll
        for (int ns = 0; ns < 8; ns++) {
            const int c0 = n0 + wn * 64 + ns * 8 + 2 * tig;
            if (c0 < VV) {
                C[(size_t)r0 * VV + c0]       = acc[ms][ns][0];
                C[(size_t)(r0 + 8) * VV + c0] = acc[ms][ns][2];
            }
            if (c0 + 1 < VV) {
                C[(size_t)r0 * VV + c0 + 1]       = acc[ms][ns][1];
                C[(size_t)(r0 + 8) * VV + c0 + 1] = acc[ms][ns][3];
            }
        }
    }
}

// =============================================================================
// beta^T fp16: beta [200 x 50000] fp32 -> betaT [50048 x 224] fp16 (zero pad).
// 32x32 smem tiles. grid (1564, 7), block 256.
// =============================================================================
__global__ void __launch_bounds__(256)
transpose_beta(const float* __restrict__ beta)
{
    __shared__ float s[32][33];
    const int tid = threadIdx.x;
    const int tx = tid & 31, ty = tid >> 5;          // 32 x 8
    const int v0 = blockIdx.x * 32, k0 = blockIdx.y * 32;

#pragma unroll
    for (int i = 0; i < 4; i++) {
        int k = ty + i * 8;
        int gk = k0 + k, gv = v0 + tx;
        float val = 0.f;
        if (gk < KK && gv < VV) val = beta[(size_t)gk * VV + gv];
        s[k][tx] = val;
    }
    __syncthreads();

#pragma unroll
    for (int i = 0; i < 2; i++) {
        int w = tid + i * 256;        // 512 words: 32 v-rows x 16 words
        int v = w >> 4, kw = w & 15;
        uint32_t word = pk_h2(__float2half_rn(s[2 * kw][v]),
                              __float2half_rn(s[2 * kw + 1][v]));
        g_bf[W_BT + (size_t)(v0 + v) * KRW + (k0 >> 1) + kw] = word;
    }
}

// ============================ bf16x3 NT GEMM (en2 + logits) ==================
#define NTB_SMEM (2 * 10240 * 4)

template<bool SP, bool HB, bool CHKMN>
__global__ void __launch_bounds__(512, 1)
gemm_nt_bf16x3(const float* __restrict__ A, const float* __restrict__ B,
               const float* __restrict__ bias, float* __restrict__ C,
               int M, int N, int K)
{
    extern __shared__ __align__(16) uint32_t sw[];
    const int tid = threadIdx.x;
    const int lane = tid & 31, warp = tid >> 5;
    const int gid = lane >> 2, tig = lane & 3;
    const int wm = warp >> 2, wn = warp & 3;
    const int m0 = blockIdx.y * 128, n0 = blockIdx.x * 128;
    const int nt = (K + 31) / 32;

    float acc[2][4][4];
#pragma unroll
    for (int i = 0; i < 2; i++)
#pragma unroll
        for (int j = 0; j < 4; j++)
#pragma unroll
            for (int l = 0; l < 4; l++) acc[i][j][l] = 0.0f;

    const int srow = tid >> 3;
    const int sq   = tid & 7;
    float4 stA[2], stB[2];

    auto load_tile = [&](int t) {
        const int gk = t * 32 + sq * 4;
#pragma unroll
        for (int l = 0; l < 2; l++) {
            int r = srow + l * 64;
            {
                int gm = m0 + r;
                float4 v = make_float4(0.f, 0.f, 0.f, 0.f);
                if (((!CHKMN) || gm < M)) {
                    if (gk + 3 < K) v = *reinterpret_cast<const float4*>(A + (size_t)gm * K + gk);
                    else if (gk < K) {
                        const float* p = A + (size_t)gm * K;
                        v.x = p[gk];
                        if (gk + 1 < K) v.y = p[gk + 1];
                        if (gk + 2 < K) v.z = p[gk + 2];
                    }
                }
                stA[l] = v;
            }
            {
                int gn = n0 + r;
                float4 v = make_float4(0.f, 0.f, 0.f, 0.f);
                if (((!CHKMN) || gn < N)) {
                    if (gk + 3 < K) v = *reinterpret_cast<const float4*>(B + (size_t)gn * K + gk);
                    else if (gk < K) {
                        const float* p = B + (size_t)gn * K;
                        v.x = p[gk];
                        if (gk + 1 < K) v.y = p[gk + 1];
                        if (gk + 2 < K) v.z = p[gk + 2];
                    }
                }
                stB[l] = v;
            }
        }
    };

    auto store_tile = [&](uint32_t* buf) {
#pragma unroll
        for (int l = 0; l < 2; l++) {
            int r = srow + l * 64;
            uint32_t w = (uint32_t)(r * 20 + sq * 2);
            {
                float4 v = stA[l];
                __nv_bfloat16 hx = __float2bfloat16_rn(v.x), hy = __float2bfloat16_rn(v.y);
                __nv_bfloat16 hz = __float2bfloat16_rn(v.z), hw = __float2bfloat16_rn(v.w);
                buf[w]     = ((uint32_t)__bfloat16_as_ushort(hy) << 16) | __bfloat16_as_ushort(hx);
                buf[w + 1] = ((uint32_t)__bfloat16_as_ushort(hw) << 16) | __bfloat16_as_ushort(hz);
                buf[w + 2560]     = pk_bf16(v.x - __bfloat162float(hx), v.y - __bfloat162float(hy));
                buf[w + 2560 + 1] = pk_bf16(v.z - __bfloat162float(hz), v.w - __bfloat162float(hw));
            }
            {
                float4 v = stB[l];
                __nv_bfloat16 hx = __float2bfloat16_rn(v.x), hy = __float2bfloat16_rn(v.y);
                __nv_bfloat16 hz = __float2bfloat16_rn(v.z), hw = __float2bfloat16_rn(v.w);
                buf[w + 5120]     = ((uint32_t)__bfloat16_as_ushort(hy) << 16) | __bfloat16_as_ushort(hx);
                buf[w + 5120 + 1] = ((uint32_t)__bfloat16_as_ushort(hw) << 16) | __bfloat16_as_ushort(hz);
                buf[w + 7680]     = pk_bf16(v.x - __bfloat162float(hx), v.y - __bfloat162float(hy));
                buf[w + 7680 + 1] = pk_bf16(v.z - __bfloat162float(hz), v.w - __bfloat162float(hw));
            }
        }
    };

    load_tile(0);
    store_tile(sw);
    __syncthreads();

    for (int t = 0; t < nt; t++) {
        const int b = t & 1;
        uint32_t* bb = sw + b * 10240;
        if (t + 1 < nt) load_tile(t + 1);

#pragma unroll
        for (int kkw = 0; kkw < 16; kkw += 8) {
            uint32_t ah[2][4], al[2][4], bh[4][2], bl[4][2];
#pragma unroll
            for (int ms = 0; ms < 2; ms++) {
                int base = (wm * 32 + ms * 16 + gid) * 20 + kkw + tig;
                ah[ms][0] = bb[base];       ah[ms][1] = bb[base + 160];
                ah[ms][2] = bb[base + 4];   ah[ms][3] = bb[base + 164];
                al[ms][0] = bb[base + 2560];       al[ms][1] = bb[base + 2560 + 160];
                al[ms][2] = bb[base + 2560 + 4];   al[ms][3] = bb[base + 2560 + 164];
            }
#pragma unroll
            for (int ns = 0; ns < 4; ns++) {
                int base = 5120 + (wn * 32 + ns * 8 + gid) * 20 + kkw + tig;
                bh[ns][0] = bb[base];       bh[ns][1] = bb[base + 4];
                bl[ns][0] = bb[base + 2560]; bl[ns][1] = bb[base + 2560 + 4];
            }
#pragma unroll
            for (int ms = 0; ms < 2; ms++)
#pragma unroll
                for (int ns = 0; ns < 4; ns++) {
                    mma_bf16(acc[ms][ns], ah[ms][0], ah[ms][1], ah[ms][2], ah[ms][3],
                             bh[ns][0], bh[ns][1]);
                    mma_bf16(acc[ms][ns], ah[ms][0], ah[ms][1], ah[ms][2], ah[ms][3],
                             bl[ns][0], bl[ns][1]);
                    mma_bf16(acc[ms][ns], al[ms][0], al[ms][1], al[ms][2], al[ms][3],
                             bh[ns][0], bh[ns][1]);
                }
        }

        if (t + 1 < nt) store_tile(sw + (b ^ 1) * 10240);
        __syncthreads();
    }

#pragma unroll
    for (int ms = 0; ms < 2; ms++) {
        int r0 = m0 + wm * 32 + ms * 16 + gid;
#pragma unroll
        for (int ns = 0; ns < 4; ns++) {
            int c0 = n0 + wn * 32 + ns * 8 + 2 * tig;
            float bv0 = 0.f, bv1 = 0.f;
            if (HB) { bv0 = bias[c0]; bv1 = bias[c0 + 1]; }
            float v00 = acc[ms][ns][0] + bv0;
            float v01 = acc[ms][ns][1] + bv1;
            float v10 = acc[ms][ns][2] + bv0;
            float v11 = acc[ms][ns][3] + bv1;
            if (SP) { v00 = softplusf(v00); v01 = softplusf(v01);
                      v10 = softplusf(v10); v11 = softplusf(v11); }
            if (!CHKMN) {
                C[(size_t)r0 * N + c0]           = v00;
                C[(size_t)r0 * N + c0 + 1]       = v01;
                C[(size_t)(r0 + 8) * N + c0]     = v10;
                C[(size_t)(r0 + 8) * N + c0 + 1] = v11;
            } else {
                if (r0 < M) {
                    if (c0 < N)     C[(size_t)r0 * N + c0]     = v00;
                    if (c0 + 1 < N) C[(size_t)r0 * N + c0 + 1] = v01;
                }
                if (r0 + 8 < M) {
                    if (c0 < N)     C[(size_t)(r0 + 8) * N + c0]     = v10;
                    if (c0 + 1 < N) C[(size_t)(r0 + 8) * N + c0 + 1] = v11;
                }
            }
        }
    }
}

// ---------------- mean / logvar heads ---------------------------------------
__global__ void meanlogvar_kernel(const float* __restrict__ en2,
                                  const float* __restrict__ mW, const float* __restrict__ mb,
                                  const float* __restrict__ lW, const float* __restrict__ lb,
                                  float* __restrict__ pm, float* __restrict__ lv)
{
    int t = blockIdx.x * blockDim.x + threadIdx.x;
    if (t >= NB * 4) return;
    int n = t >> 2, j = t & 3;
    const float* w = (j < 2) ? (mW + j * E2) : (lW + (j - 2) * E2);
    const float* x = en2 + (size_t)n * E2;
    float s = 0.f;
    for (int i = 0; i < E2; i += 4) {
        float4 xa = *reinterpret_cast<const float4*>(x + i);
        float4 wa = *reinterpret_cast<const float4*>(w + i);
        s += xa.x * wa.x + xa.y * wa.y + xa.z * wa.z + xa.w * wa.w;
    }
    if (j < 2) pm[n * 2 + j] = s + mb[j];
    else       lv[n * 2 + (j - 2)] = s + lb[j - 2];
}

// ---------------- column stats of (R x 2) -----------------------------------
__global__ void colstats_kernel(const float* __restrict__ X, int R, float* __restrict__ out)
{
    __shared__ float ss[256], s2[256];
    int c = blockIdx.x, tid = threadIdx.x;
    float s = 0.f, q = 0.f;
    for (int r = tid; r < R; r += 256) {
        float x = X[r * 2 + c];
        s += x; q += x * x;
    }
    ss[tid] = s; s2[tid] = q;
    __syncthreads();
    for (int st = 128; st > 0; st >>= 1) {
        if (tid < st) { ss[tid] += ss[tid + st]; s2[tid] += s2[tid + st]; }
        __syncthreads();
    }
    if (tid == 0) {
        float m = ss[0] / R;
        out[c] = m;
        out[2 + c] = s2[0] / R - m * m;
    }
}

// ---------------- z ----------------------------------------------------------
__global__ void z_kernel(const float* __restrict__ pm, const float* __restrict__ lv,
                         const float* __restrict__ spm, const float* __restrict__ slv,
                         const float* __restrict__ gm, const float* __restrict__ bm,
                         const float* __restrict__ gl, const float* __restrict__ bl,
                         const float* __restrict__ eps,
                         float* __restrict__ gz, float* __restrict__ outz)
{
    int idx = blockIdx.x * 256 + threadIdx.x;
    if (idx >= NB * CC) return;
    int c = idx & 1;
    float pmb = gm[c] * (pm[idx] - spm[c]) * rsqrtf(spm[2 + c] + 1e-5f) + bm[c];
    float lvb = gl[c] * (lv[idx] - slv[c]) * rsqrtf(slv[2 + c] + 1e-5f) + bl[c];
    float z = pmb + sqrtf(expf(lvb)) * eps[idx];
    gz[idx] = z;
    outz[idx] = z;
}

// ---------------- BN apply ---------------------------------------------------
__global__ void bn_apply_kernel(const float* __restrict__ X, const float* __restrict__ stats,
                                const float* __restrict__ g, const float* __restrict__ b,
                                int total, float* __restrict__ o1, float* __restrict__ o2)
{
    int idx = blockIdx.x * 256 + threadIdx.x;
    if (idx >= total) return;
    int c = idx & 1;
    float y = g[c] * (X[idx] - stats[c]) * rsqrtf(stats[2 + c] + 1e-5f) + b[c];
    o1[idx] = y;
    o2[idx] = y;
}

// ---------------- theta (also emits fp16 plane, zero-padded to 224) ---------
__global__ void theta_kernel(const float* __restrict__ zx, const float* __restrict__ zc,
                             float* __restrict__ gtheta, float* __restrict__ otheta)
{
    __shared__ float sz[KK * 2];
    __shared__ float red[256];
    __shared__ float sth[KR];
    int n = blockIdx.x, tid = threadIdx.x;
    for (int i = tid; i < KK * 2; i += 256) sz[i] = zc[i];
    __syncthreads();
    float x0 = zx[n * 2], x1 = zx[n * 2 + 1];
    float l = -FLT_MAX;
    if (tid < KK) {
        float dx = x0 - sz[tid * 2];
        float dy = x1 - sz[tid * 2 + 1];
        l = -0.5f * (dx * dx + dy * dy);
    }
    red[tid] = l;
    __syncthreads();
    for (int st = 128; st > 0; st >>= 1) {
        if (tid < st) red[tid] = fmaxf(red[tid], red[tid + st]);
        __syncthreads();
    }
    float mx = red[0];
    __syncthreads();
    float e = (tid < KK) ? expf(l - mx) : 0.f;
    red[tid] = e;
    __syncthreads();
    for (int st = 128; st > 0; st >>= 1) {
        if (tid < st) red[tid] += red[tid + st];
        __syncthreads();
    }
    float inv = 1.f / red[0];
    float th = e * inv;
    if (tid < KK) {
        gtheta[(size_t)n * KK + tid] = th;
        otheta[(size_t)n * KK + tid] = th;
    }
    if (tid < KR) sth[tid] = (tid < KK) ? th : 0.f;
    __syncthreads();
    if (tid < KRW) {
        g_bf[W_TH + (size_t)n * KRW + tid] =
            pk_h2(__float2half_rn(sth[2 * tid]), __float2half_rn(sth[2 * tid + 1]));
    }
}

// ---------------- decoder MLP ------------------------------------------------
__global__ void mu1_kernel(const float* __restrict__ zc, const float* __restrict__ W,
                           const float* __restrict__ b, float* __restrict__ out)
{
    int t = blockIdx.x * 256 + threadIdx.x;
    if (t >= KK * 100) return;
    int k = t / 100, j = t % 100;
    float v = zc[k * 2] * W[j * 2] + zc[k * 2 + 1] * W[j * 2 + 1] + b[j];
    out[t] = softplusf(v);
}

__global__ void mu2_kernel(const float* __restrict__ mu1, const float* __restrict__ W,
                           const float* __restrict__ b, float* __restrict__ out)
{
    __shared__ float row[100];
    int k = blockIdx.x, tid = threadIdx.x;
    if (tid < 100) row[tid] = mu1[k * 100 + tid];
    __syncthreads();
    if (tid < 100) {
        const float* w = W + tid * 100;
        float s = b[tid];
        for (int i = 0; i < 100; i++) s += row[i] * w[i];
        out[k * 100 + tid] = softplusf(s);
    }
}

__global__ void muz_kernel(const float* __restrict__ mu2, const float* __restrict__ W,
                           const float* __restrict__ b, float* __restrict__ out)
{
    __shared__ float row[100];
    int k = blockIdx.x, tid = threadIdx.x;
    if (tid < 100) row[tid] = mu2[k * 100 + tid];
    __syncthreads();
    for (int j = tid; j < EMB; j += 128) {
        const float* w = W + j * 100;
        float s = b[j];
        for (int i = 0; i < 100; i++) s += row[i] * w[i];
        out[k * EMB + j] = s;
    }
}

// ---------------- beta -------------------------------------------------------
__global__ void __launch_bounds__(1024)
beta_kernel(const float* __restrict__ logits, const float* __restrict__ bbias,
            const float* __restrict__ gdec, const float* __restrict__ bdec,
            float* __restrict__ beta)
{
    __shared__ float red[1024];
    __shared__ float red2[1024];
    const int k = blockIdx.x, tid = threadIdx.x;
    const float* row = logits + (size_t)k * VV;
    const float* bb  = bbias + (size_t)k * VV;

    float s = 0.f, q = 0.f;
    for (int v = tid; v < VV; v += 1024) { float x = row[v]; s += x; q += x * x; }
    red[tid] = s; red2[tid] = q;
    __syncthreads();
    for (int st = 512; st > 0; st >>= 1) {
        if (tid < st) { red[tid] += red[tid + st]; red2[tid] += red2[tid + st]; }
        __syncthreads();
    }
    float mean = red[0] / VV;
    float var  = red2[0] / VV - mean * mean;
    float scale = gdec[k] * rsqrtf(var + 1e-5f);
    float shift = bdec[k] - mean * scale;
    __syncthreads();

    float mx = -FLT_MAX;
    for (int v = tid; v < VV; v += 1024) {
        float y = row[v] * scale + shift + bb[v];
        mx = fmaxf(mx, y);
    }
    red[tid] = mx;
    __syncthreads();
    for (int st = 512; st > 0; st >>= 1) {
        if (tid < st) red[tid] = fmaxf(red[tid], red[tid + st]);
        __syncthreads();
    }
    mx = red[0];
    __syncthreads();

    float se = 0.f;
    for (int v = tid; v < VV; v += 1024) {
        float y = row[v] * scale + shift + bb[v];
        se += expf(y - mx);
    }
    red[tid] = se;
    __syncthreads();
    for (int st = 512; st > 0; st >>= 1) {
        if (tid < st) red[tid] += red[tid + st];
        __syncthreads();
    }
    float inv = 1.f / red[0];

    for (int v = tid; v < VV; v += 1024) {
        float y = row[v] * scale + shift + bb[v];
        beta[(size_t)k * VV + v] = expf(y - mx) * inv;
    }
}

// ---------------- launch -----------------------------------------------------
extern "C" void kernel_launch(void* const* d_in, const int* in_sizes, int n_in,
                              void* d_out, int out_size)
{
    const float* input_   = (const float*)d_in[0];
    const float* eps      = (const float*)d_in[2];
    const float* en1_W    = (const float*)d_in[3];
    const float* en1_b    = (const float*)d_in[4];
    const float* en2_W    = (const float*)d_in[5];
    const float* en2_b    = (const float*)d_in[6];
    const float* mean_W   = (const float*)d_in[7];
    const float* mean_b   = (const float*)d_in[8];
    const float* logvar_W = (const float*)d_in[9];
    const float* logvar_b = (const float*)d_in[10];
    const float* mu1_W    = (const float*)d_in[11];
    const float* mu1_b    = (const float*)d_in[12];
    const float* mu2_W    = (const float*)d_in[13];
    const float* mu2_b    = (const float*)d_in[14];
    const float* mu_W     = (const float*)d_in[15];
    const float* mu_b     = (const float*)d_in[16];
    const float* topics   = (const float*)d_in[17];
    const float* bbias    = (const float*)d_in[18];
    const float* emb      = (const float*)d_in[19];
    const float* g_mean   = (const float*)d_in[20];
    const float* b_mean   = (const float*)d_in[21];
    const float* g_logvar = (const float*)d_in[22];
    const float* b_logvar = (const float*)d_in[23];
    const float* g_x      = (const float*)d_in[24];
    const float* b_x      = (const float*)d_in[25];
    const float* g_phi    = (const float*)d_in[26];
    const float* b_phi    = (const float*)d_in[27];
    const float* g_dec    = (const float*)d_in[28];
    const float* b_dec    = (const float*)d_in[29];

    float* out = (float*)d_out;
    float* out_z     = out;
    float* out_recon = out + (long long)NB * CC;
    float* out_zx    = out_recon + (long long)NB * VV;
    float* out_zc    = out_zx + (long long)NB * CC;
    float* out_theta = out_zc + (long long)KK * CC;

    void* sp = nullptr;
    cudaGetSymbolAddress(&sp, g_scratch);
    float* S = (float*)sp;
    float* s_en1    = S + OFF_EN1;
    float* s_en2    = S + OFF_EN2;
    float* s_pm     = S + OFF_PM;
    float* s_lv     = S + OFF_LV;
    float* s_z      = S + OFF_Z;
    float* s_zx     = S + OFF_ZX;
    float* s_zc     = S + OFF_ZC;
    float* s_theta  = S + OFF_THETA;
    float* s_mu1    = S + OFF_MU1;
    float* s_mu2    = S + OFF_MU2;
    float* s_muz    = S + OFF_MUZ;
    float* s_logits = S + OFF_LOGITS;
    float* s_beta   = S + OFF_BETA;
    float* st_pm    = S + OFF_SPM;
    float* st_lv    = S + OFF_SLV;
    float* st_z     = S + OFF_SZ;
    float* st_t     = S + OFF_ST;

    cudaFuncSetAttribute(gemm1_fp16, cudaFuncAttributeMaxDynamicSharedMemorySize, G1_SMEM);
    cudaFuncSetAttribute(recon_f16, cudaFuncAttributeMaxDynamicSharedMemorySize, G1_SMEM);
    cudaFuncSetAttribute(gemm_nt_bf16x3<true, true, false>,
                         cudaFuncAttributeMaxDynamicSharedMemorySize, NTB_SMEM);
    cudaFuncSetAttribute(gemm_nt_bf16x3<false, false, true>,
                         cudaFuncAttributeMaxDynamicSharedMemorySize, NTB_SMEM);

    // 0) pre-split: A -> 1 fp16 plane, B -> 1 fp16 plane
    split_fp16<<<NB + E1, 256>>>(input_, en1_W);

    // 1-4) decoder-side small kernels
    colstats_kernel<<<2, 256>>>(topics, KK, st_t);
    bn_apply_kernel<<<(KK * CC + 255) / 256, 256>>>(topics, st_t, g_phi, b_phi, KK * CC, s_zc, out_zc);
    mu1_kernel<<<(KK * 100 + 255) / 256, 256>>>(s_zc, mu1_W, mu1_b, s_mu1);
    mu2_kernel<<<KK, 128>>>(s_mu1, mu2_W, mu2_b, s_mu2);

    // 5) en1 = softplus(input @ en1_W^T + b) — plain fp16
    gemm1_fp16<<<dim3(E1 / 128, NB / 128), 256, G1_SMEM>>>(en1_b, s_en1);

    // 6) muz
    muz_kernel<<<KK, 128>>>(s_mu2, mu_W, mu_b, s_muz);

    // 7) en2 — bf16x3
    gemm_nt_bf16x3<true, true, false><<<dim3(E2 / 128, NB / 128), 512, NTB_SMEM>>>(
        s_en1, en2_W, en2_b, s_en2, NB, E2, E1);

    // 8) heads
    meanlogvar_kernel<<<(NB * 4 + 255) / 256, 256>>>(
        s_en2, mean_W, mean_b, logvar_W, logvar_b, s_pm, s_lv);

    // 9-11) BN stats + z
    colstats_kernel<<<2, 256>>>(s_pm, NB, st_pm);
    colstats_kernel<<<2, 256>>>(s_lv, NB, st_lv);
    z_kernel<<<(NB * CC + 255) / 256, 256>>>(
        s_pm, s_lv, st_pm, st_lv, g_mean, b_mean, g_logvar, b_logvar, eps, s_z, out_z);

    // 12-13) zx
    colstats_kernel<<<2, 256>>>(s_z, NB, st_z);
    bn_apply_kernel<<<(NB * CC + 255) / 256, 256>>>(s_z, st_z, g_x, b_x, NB * CC, s_zx, out_zx);

    // 14) theta (fp32 outputs + fp16 plane)
    theta_kernel<<<NB, 256>>>(s_zx, s_zc, s_theta, out_theta);

    // 15) logits = mu_z @ emb^T — bf16x3
    gemm_nt_bf16x3<false, false, true><<<dim3((VV + 127) / 128, (KK + 127) / 128), 512, NTB_SMEM>>>(
        s_muz, emb, nullptr, s_logits, KK, VV, EMB);

    // 16) beta
    beta_kernel<<<KK, 1024>>>(s_logits, bbias, g_dec, b_dec, s_beta);

    // 17) beta^T fp16
    transpose_beta<<<dim3(BTROWS / 32, KR / 32), 256>>>(s_beta);

    // 18) recon = theta @ beta — fp16 NT
    recon_f16<<<dim3(BTROWS / 128, NB / 128), 256, G1_SMEM>>>(out_recon);

    (void)in_sizes; (void)n_in; (void)out_size;
}